// round 6
// baseline (speedup 1.0000x reference)
#include <cuda_runtime.h>
#include <cuda_fp16.h>
#include <mma.h>

using namespace nvcuda;

#define N_NODES 50000
#define N_EDGES 800000
#define HDIM    128
#define NPAD    50048           // ceil(N/128)*128
#define WSZ     (HDIM * HDIM)

// ---------------- scratch (device globals; no allocation allowed) ----------
__device__ __half g_xh   [NPAD * HDIM];
__device__ float  g_xd   [NPAD * HDIM];              // x @ We0 (fp32)
__device__ __half g_xsh  [NPAD * HDIM];              // half(x @ We1)
__device__ __half g_aggh [NPAD * HDIM];              // half(segment_sum)
__device__ __half g_hWh  [NPAD * HDIM];              // half(agg @ Wc + bgwo)
__device__ __half g_eawh [(size_t)N_EDGES * HDIM];   // half(ea @ We2), CSR order
__device__ __half g_Weh  [3 * WSZ];
__device__ __half g_Wch  [WSZ];                      // half(Wg@Wo)
__device__ float  g_bgwo [HDIM];                     // bg@Wo
// CSR machinery
__device__ int g_deg_in [N_NODES];
__device__ int g_deg_out[N_NODES];
__device__ int g_off_in [N_NODES + 1];
__device__ int g_off_out[N_NODES + 1];
__device__ int g_cur_in [N_NODES];
__device__ int g_cur_out[N_NODES];
__device__ int g_csr_in_src[N_EDGES];   // in-CSR: source node per in-edge
__device__ int g_csr_in_eid[N_EDGES];   // in-CSR: original edge id
__device__ int g_csr_out_dst[N_EDGES];  // out-CSR: dest node per out-edge

// ---------------- small utility kernels ------------------------------------
__global__ void k_zerodeg(int* __restrict__ din, int* __restrict__ dout) {
    int i = blockIdx.x * blockDim.x + threadIdx.x;
    if (i < N_NODES) { din[i] = 0; dout[i] = 0; }
}

__global__ void k_hist(const int* __restrict__ ei, int* __restrict__ din, int* __restrict__ dout) {
    int e = blockIdx.x * 256 + threadIdx.x;
    if (e >= N_EDGES) return;
    atomicAdd(&dout[ei[e]], 1);            // src
    atomicAdd(&din[ei[N_EDGES + e]], 1);   // dst
}

// 2-block kernel: block 0 scans in-degrees, block 1 scans out-degrees
__global__ void k_scan2(const int* __restrict__ din, int* __restrict__ oin, int* __restrict__ cin,
                        const int* __restrict__ dout, int* __restrict__ oout, int* __restrict__ cout_) {
    const int* deg = blockIdx.x ? dout : din;
    int* off = blockIdx.x ? oout : oin;
    int* cur = blockIdx.x ? cout_ : cin;

    __shared__ int sp[1024];
    const int t = threadIdx.x;
    const int CH = 49;                               // 1024*49 >= 50000
    int start = t * CH;
    int end   = start + CH; if (end > N_NODES) end = N_NODES;
    int sum = 0;
    for (int i = start; i < end; i++) sum += deg[i];
    sp[t] = sum;
    __syncthreads();
    for (int d = 1; d < 1024; d <<= 1) {
        int v = (t >= d) ? sp[t - d] : 0;
        __syncthreads();
        sp[t] += v;
        __syncthreads();
    }
    int run = (t == 0) ? 0 : sp[t - 1];
    for (int i = start; i < end; i++) { off[i] = run; cur[i] = run; run += deg[i]; }
    if (start < N_NODES && end == N_NODES) off[N_NODES] = run;
}

__global__ void k_scatteridx(const int* __restrict__ ei,
                             int* __restrict__ cin, int* __restrict__ cout_,
                             int* __restrict__ isrc, int* __restrict__ ieid,
                             int* __restrict__ odst) {
    int e = blockIdx.x * 256 + threadIdx.x;
    if (e >= N_EDGES) return;
    int s = ei[e];
    int d = ei[N_EDGES + e];
    int p1 = atomicAdd(&cin[d], 1);
    isrc[p1] = s; ieid[p1] = e;
    int p2 = atomicAdd(&cout_[s], 1);
    odst[p2] = d;
}

__global__ void k_f2h(const float* __restrict__ s, __half* __restrict__ d, int n, int ntot) {
    int i = blockIdx.x * blockDim.x + threadIdx.x;
    if (i < ntot) d[i] = (i < n) ? __float2half(s[i]) : __half(0.f);
}

// Wc = Wg @ Wo  (fp32 accumulate, round once to half)
__global__ void k_wc(const float* __restrict__ Wg, const float* __restrict__ Wo,
                     __half* __restrict__ Wch) {
    int i = blockIdx.x * blockDim.x + threadIdx.x;
    int r = i >> 7, c = i & 127;
    float s = 0.f;
#pragma unroll 8
    for (int k = 0; k < 128; k++) s += Wg[r * 128 + k] * Wo[k * 128 + c];
    Wch[i] = __float2half(s);
}

__global__ void k_bgwo(const float* __restrict__ bg, const float* __restrict__ Wo,
                       float* __restrict__ bgwo) {
    int c = threadIdx.x;
    float s = 0.f;
#pragma unroll 8
    for (int k = 0; k < 128; k++) s += bg[k] * Wo[k * 128 + c];
    bgwo[c] = s;
}

// ---------------- [128rows,128]@[128,128] GEMM, B staged in shared ---------
// HALF_OUT selects fp32 or half output. All written rows exist (padded bufs).
template <bool HALF_OUT>
__global__ void k_gemm(const __half* __restrict__ A, const __half* __restrict__ B,
                       const float* __restrict__ bias, void* __restrict__ C) {
    extern __shared__ char smem[];
    __half* sB = reinterpret_cast<__half*>(smem);    // 128 x 136 halves
    float*  sT = reinterpret_cast<float*>(smem);     // reused for staging out

    const int tid  = threadIdx.x;
    const int warp = tid >> 5;
    const int lane = tid & 31;

#pragma unroll
    for (int j = 0; j < 32; j++) {                   // 8192 half2
        int idx = j * 256 + tid;
        int row = idx >> 6, c2 = idx & 63;
        *reinterpret_cast<__half2*>(sB + row * 136 + c2 * 2) =
            *reinterpret_cast<const __half2*>(B + row * 128 + c2 * 2);
    }
    __syncthreads();

    const int row0 = blockIdx.x * 128 + warp * 16;
    wmma::fragment<wmma::accumulator, 16, 16, 16, float> acc[8];
#pragma unroll
    for (int n = 0; n < 8; n++) wmma::fill_fragment(acc[n], 0.f);

#pragma unroll
    for (int k = 0; k < 8; k++) {
        wmma::fragment<wmma::matrix_a, 16, 16, 16, __half, wmma::row_major> a;
        wmma::load_matrix_sync(a, A + (size_t)row0 * 128 + k * 16, 128);
#pragma unroll
        for (int n = 0; n < 8; n++) {
            wmma::fragment<wmma::matrix_b, 16, 16, 16, __half, wmma::row_major> b;
            wmma::load_matrix_sync(b, sB + (k * 16) * 136 + n * 16, 136);
            wmma::mma_sync(acc[n], a, b, acc[n]);
        }
    }
    __syncthreads();                                 // done with sB

    float* my = sT + warp * 16 * 132;
#pragma unroll
    for (int n = 0; n < 8; n++)
        wmma::store_matrix_sync(my + n * 16, acc[n], 132, wmma::mem_row_major);
    __syncwarp();

    float4 bv = make_float4(0.f, 0.f, 0.f, 0.f);
    if (bias) bv = *reinterpret_cast<const float4*>(bias + lane * 4);

#pragma unroll
    for (int r = 0; r < 16; r++) {
        float4 v = *reinterpret_cast<const float4*>(my + r * 132 + lane * 4);
        v.x += bv.x; v.y += bv.y; v.z += bv.z; v.w += bv.w;
        if (HALF_OUT) {
            __half2* pc = reinterpret_cast<__half2*>((__half*)C + (size_t)(row0 + r) * 128 + lane * 4);
            pc[0] = __floats2half2_rn(v.x, v.y);
            pc[1] = __floats2half2_rn(v.z, v.w);
        } else {
            *reinterpret_cast<float4*>((float*)C + (size_t)(row0 + r) * 128 + lane * 4) = v;
        }
    }
}

// ---------------- eaW[csr_pos] = half(ea[eid] @ We2) -----------------------
// A rows gathered by in-CSR edge id; output sequential in CSR order.
__global__ void k_eaw(const float* __restrict__ ea, const int* __restrict__ ieid,
                      const __half* __restrict__ W2, __half* __restrict__ eaw) {
    extern __shared__ char smem[];
    __half* sA   = reinterpret_cast<__half*>(smem);            // 128 x 136
    __half* sB   = reinterpret_cast<__half*>(smem + 34816);    // 128 x 136
    int*    sEid = reinterpret_cast<int*>(smem + 69632);       // 128 ints
    float*  sT   = reinterpret_cast<float*>(smem);             // reused

    const int tid  = threadIdx.x;
    const int warp = tid >> 5;
    const size_t p0 = (size_t)blockIdx.x * 128;      // CSR position base

    if (tid < 128) sEid[tid] = ieid[p0 + tid];
#pragma unroll
    for (int j = 0; j < 32; j++) {                   // stage W2
        int idx = j * 256 + tid;
        int row = idx >> 6, c2 = idx & 63;
        *reinterpret_cast<__half2*>(sB + row * 136 + c2 * 2) =
            *reinterpret_cast<const __half2*>(W2 + row * 128 + c2 * 2);
    }
    __syncthreads();

#pragma unroll
    for (int j = 0; j < 16; j++) {                   // gather A tile rows
        int idx = j * 256 + tid;
        int row = idx >> 5, c4 = idx & 31;
        const float* rp = ea + (size_t)sEid[row] * 128;
        float4 v = *reinterpret_cast<const float4*>(rp + c4 * 4);
        *reinterpret_cast<__half2*>(sA + row * 136 + c4 * 4)     = __floats2half2_rn(v.x, v.y);
        *reinterpret_cast<__half2*>(sA + row * 136 + c4 * 4 + 2) = __floats2half2_rn(v.z, v.w);
    }
    __syncthreads();

    wmma::fragment<wmma::accumulator, 16, 16, 16, float> acc[8];
#pragma unroll
    for (int n = 0; n < 8; n++) wmma::fill_fragment(acc[n], 0.f);

#pragma unroll
    for (int k = 0; k < 8; k++) {
        wmma::fragment<wmma::matrix_a, 16, 16, 16, __half, wmma::row_major> a;
        wmma::load_matrix_sync(a, sA + warp * 16 * 136 + k * 16, 136);
#pragma unroll
        for (int n = 0; n < 8; n++) {
            wmma::fragment<wmma::matrix_b, 16, 16, 16, __half, wmma::row_major> b;
            wmma::load_matrix_sync(b, sB + (k * 16) * 136 + n * 16, 136);
            wmma::mma_sync(acc[n], a, b, acc[n]);
        }
    }
    __syncthreads();                                 // done reading sA/sB

    float* my = sT + warp * 16 * 132;
#pragma unroll
    for (int n = 0; n < 8; n++)
        wmma::store_matrix_sync(my + n * 16, acc[n], 132, wmma::mem_row_major);
    __syncthreads();                                 // write loop spans all warps

#pragma unroll
    for (int j = 0; j < 32; j++) {                   // 8192 half2 out, sequential
        int idx = j * 256 + tid;
        int row = idx >> 6, c2 = idx & 63;
        float x0 = sT[row * 132 + c2 * 2];
        float x1 = sT[row * 132 + c2 * 2 + 1];
        *reinterpret_cast<__half2*>(eaw + (p0 + row) * 128 + c2 * 2) = __floats2half2_rn(x0, x1);
    }
}

// ---------------- aggregation: aggh[n] = half(sum_in silu(xd[n]+be + xs[s] + eaW)) 
__device__ __forceinline__ float silu1(float v) { return v / (1.f + __expf(-v)); }

__global__ void k_agg(const int* __restrict__ off, const int* __restrict__ csrs,
                      const float* __restrict__ xd, const __half* __restrict__ xsh,
                      const __half* __restrict__ eaw, const float* __restrict__ be,
                      __half* __restrict__ aggh) {
    const int w    = (blockIdx.x * 256 + threadIdx.x) >> 5;    // node id
    const int lane = threadIdx.x & 31;
    if (w >= N_NODES) return;

    float4 base = *reinterpret_cast<const float4*>(xd + (size_t)w * 128 + lane * 4);
    float4 bb   = *reinterpret_cast<const float4*>(be + lane * 4);
    base.x += bb.x; base.y += bb.y; base.z += bb.z; base.w += bb.w;

    float4 acc = make_float4(0.f, 0.f, 0.f, 0.f);
    const int beg = off[w], end = off[w + 1];
#pragma unroll 4
    for (int i = beg; i < end; i++) {
        int s = csrs[i];
        const __half2* pv = reinterpret_cast<const __half2*>(xsh + (size_t)s * 128 + lane * 4);
        const __half2* pe = reinterpret_cast<const __half2*>(eaw + (size_t)i * 128 + lane * 4);
        float2 v0 = __half22float2(pv[0]);
        float2 v1 = __half22float2(pv[1]);
        float2 e0 = __half22float2(pe[0]);
        float2 e1 = __half22float2(pe[1]);
        acc.x += silu1(base.x + v0.x + e0.x);
        acc.y += silu1(base.y + v0.y + e0.y);
        acc.z += silu1(base.z + v1.x + e1.x);
        acc.w += silu1(base.w + v1.y + e1.y);
    }
    __half2* pa = reinterpret_cast<__half2*>(aggh + (size_t)w * 128 + lane * 4);
    pa[0] = __floats2half2_rn(acc.x, acc.y);
    pa[1] = __floats2half2_rn(acc.z, acc.w);
}

// ---------------- output: out[n] = bo + sum_out hW[dst] ---------------------
__global__ void k_out(const int* __restrict__ off, const int* __restrict__ odst,
                      const __half* __restrict__ hWh, const float* __restrict__ bo,
                      float* __restrict__ out) {
    const int w    = (blockIdx.x * 256 + threadIdx.x) >> 5;
    const int lane = threadIdx.x & 31;
    if (w >= N_NODES) return;

    float4 acc = *reinterpret_cast<const float4*>(bo + lane * 4);
    const int beg = off[w], end = off[w + 1];
#pragma unroll 4
    for (int i = beg; i < end; i++) {
        int d = odst[i];
        const __half2* pv = reinterpret_cast<const __half2*>(hWh + (size_t)d * 128 + lane * 4);
        float2 v0 = __half22float2(pv[0]);
        float2 v1 = __half22float2(pv[1]);
        acc.x += v0.x; acc.y += v0.y; acc.z += v1.x; acc.w += v1.y;
    }
    *reinterpret_cast<float4*>(out + (size_t)w * 128 + lane * 4) = acc;
}

// ---------------- launch ----------------------------------------------------
extern "C" void kernel_launch(void* const* d_in, const int* in_sizes, int n_in,
                              void* d_out, int out_size) {
    const float* x  = (const float*)d_in[0];
    const int*   ei = (const int*)d_in[1];     // int32 (JAX x64 disabled)
    const float* ea = (const float*)d_in[2];
    const float* We = (const float*)d_in[3];
    const float* be = (const float*)d_in[4];
    const float* Wg = (const float*)d_in[5];
    const float* bg = (const float*)d_in[6];
    // d_in[7]=Wa, d_in[8]=ba: dead (softmax over size-1 axis == 1)
    const float* Wo = (const float*)d_in[9];
    const float* bo = (const float*)d_in[10];
    float*       out = (float*)d_out;

    void *p;
    __half *xh, *xsh, *aggh, *hWh, *eawh, *Weh, *Wch;
    float *xd, *bgwo;
    int *din, *dout_, *oin, *oout, *cin, *cout_, *isrc, *ieid, *odst;
    cudaGetSymbolAddress(&p, g_xh);          xh    = (__half*)p;
    cudaGetSymbolAddress(&p, g_xd);          xd    = (float*)p;
    cudaGetSymbolAddress(&p, g_xsh);         xsh   = (__half*)p;
    cudaGetSymbolAddress(&p, g_aggh);        aggh  = (__half*)p;
    cudaGetSymbolAddress(&p, g_hWh);         hWh   = (__half*)p;
    cudaGetSymbolAddress(&p, g_eawh);        eawh  = (__half*)p;
    cudaGetSymbolAddress(&p, g_Weh);         Weh   = (__half*)p;
    cudaGetSymbolAddress(&p, g_Wch);         Wch   = (__half*)p;
    cudaGetSymbolAddress(&p, g_bgwo);        bgwo  = (float*)p;
    cudaGetSymbolAddress(&p, g_deg_in);      din   = (int*)p;
    cudaGetSymbolAddress(&p, g_deg_out);     dout_ = (int*)p;
    cudaGetSymbolAddress(&p, g_off_in);      oin   = (int*)p;
    cudaGetSymbolAddress(&p, g_off_out);     oout  = (int*)p;
    cudaGetSymbolAddress(&p, g_cur_in);      cin   = (int*)p;
    cudaGetSymbolAddress(&p, g_cur_out);     cout_ = (int*)p;
    cudaGetSymbolAddress(&p, g_csr_in_src);  isrc  = (int*)p;
    cudaGetSymbolAddress(&p, g_csr_in_eid);  ieid  = (int*)p;
    cudaGetSymbolAddress(&p, g_csr_out_dst); odst  = (int*)p;

    const size_t gemm_shmem = 67584;
    const size_t eaw_shmem  = 70144;          // sA+sB (69632) + sEid (512)
    cudaFuncSetAttribute(k_gemm<false>, cudaFuncAttributeMaxDynamicSharedMemorySize, (int)gemm_shmem);
    cudaFuncSetAttribute(k_gemm<true>,  cudaFuncAttributeMaxDynamicSharedMemorySize, (int)gemm_shmem);
    cudaFuncSetAttribute(k_eaw,         cudaFuncAttributeMaxDynamicSharedMemorySize, (int)eaw_shmem);

    const int NH  = N_NODES * HDIM;
    const int NHP = NPAD * HDIM;
    const int gblocks = NPAD / 128;           // 391
    const int eblocks = N_EDGES / 128;        // 6250
    const int nwarp_blocks = (N_NODES * 32 + 255) / 256;   // 6250

    // 1-5: CSR build + weight convert
    k_zerodeg<<<(N_NODES + 255) / 256, 256>>>(din, dout_);                    // 1
    k_hist<<<(N_EDGES + 255) / 256, 256>>>(ei, din, dout_);                   // 2
    k_scan2<<<2, 1024>>>(din, oin, cin, dout_, oout, cout_);                  // 3
    k_scatteridx<<<(N_EDGES + 255) / 256, 256>>>(ei, cin, cout_, isrc, ieid, odst); // 4
    k_f2h<<<(3 * WSZ + 255) / 256, 256>>>(We, Weh, 3 * WSZ, 3 * WSZ);         // 5

    // 6: edge GEMM in CSR order (profiled by ncu -s 5 -c 1)
    k_eaw<<<eblocks, 256, eaw_shmem>>>(ea, ieid, Weh + 2 * WSZ, eawh);        // 6

    // node-side prep
    k_f2h<<<(NHP + 255) / 256, 256>>>(x, xh, NH, NHP);                        // 7
    k_wc<<<64, 256>>>(Wg, Wo, Wch);                                           // 8
    k_bgwo<<<1, 128>>>(bg, Wo, bgwo);                                         // 9
    k_gemm<false><<<gblocks, 256, gemm_shmem>>>(xh, Weh,       nullptr, xd);  // 10
    k_gemm<true ><<<gblocks, 256, gemm_shmem>>>(xh, Weh + WSZ, nullptr, xsh); // 11

    // atomic-free aggregation (sequential eaW, half xs gathers)
    k_agg<<<nwarp_blocks, 256>>>(oin, isrc, xd, xsh, eawh, be, aggh);         // 12

    // hW = agg @ (Wg@Wo) + bg@Wo, half out
    k_gemm<true><<<gblocks, 256, gemm_shmem>>>(aggh, Wch, bgwo, hWh);         // 13

    // out[n] = bo + sum hW[dst] over out-edges
    k_out<<<nwarp_blocks, 256>>>(oout, odst, hWh, bo, out);                   // 14
}

// round 8
// speedup vs baseline: 1.4107x; 1.4107x over previous
#include <cuda_runtime.h>
#include <cuda_fp16.h>
#include <mma.h>

using namespace nvcuda;

#define N_NODES 50000
#define N_EDGES 800000
#define HDIM    128
#define NPAD    50048           // ceil(N/128)*128
#define WSZ     (HDIM * HDIM)

// ---------------- scratch (device globals; no allocation allowed) ----------
__device__ __half g_xh   [NPAD * HDIM];
__device__ float  g_xd   [NPAD * HDIM];              // x @ We0 (fp32)
__device__ __half g_xsh  [NPAD * HDIM];              // half(x @ We1)
__device__ __half g_aggh [NPAD * HDIM];              // half(segment_sum)
__device__ __half g_hWh  [NPAD * HDIM];              // half(agg @ Wc + bgwo)
__device__ __half g_eawh [(size_t)N_EDGES * HDIM];   // half(ea @ We2), EDGE-ID order
__device__ __half g_Weh  [3 * WSZ];
__device__ __half g_Wch  [WSZ];                      // half(Wg@Wo)
__device__ float  g_bgwo [HDIM];                     // bg@Wo
// CSR machinery
__device__ int g_deg_in [N_NODES];
__device__ int g_deg_out[N_NODES];
__device__ int g_off_in [N_NODES + 1];
__device__ int g_off_out[N_NODES + 1];
__device__ int g_cur_in [N_NODES];
__device__ int g_cur_out[N_NODES];
__device__ int g_csr_in_src[N_EDGES];   // in-CSR: source node per in-edge
__device__ int g_csr_in_eid[N_EDGES];   // in-CSR: original edge id
__device__ int g_csr_out_dst[N_EDGES];  // out-CSR: dest node per out-edge

// ---------------- small utility kernels ------------------------------------
__global__ void k_zerodeg(int* __restrict__ din, int* __restrict__ dout) {
    int i = blockIdx.x * blockDim.x + threadIdx.x;
    if (i < N_NODES) { din[i] = 0; dout[i] = 0; }
}

__global__ void k_hist(const int* __restrict__ ei, int* __restrict__ din, int* __restrict__ dout) {
    int e = blockIdx.x * 256 + threadIdx.x;
    if (e >= N_EDGES) return;
    atomicAdd(&dout[ei[e]], 1);            // src
    atomicAdd(&din[ei[N_EDGES + e]], 1);   // dst
}

// 2-block kernel: block 0 scans in-degrees, block 1 scans out-degrees
__global__ void k_scan2(const int* __restrict__ din, int* __restrict__ oin, int* __restrict__ cin,
                        const int* __restrict__ dout, int* __restrict__ oout, int* __restrict__ cout_) {
    const int* deg = blockIdx.x ? dout : din;
    int* off = blockIdx.x ? oout : oin;
    int* cur = blockIdx.x ? cout_ : cin;

    __shared__ int sp[1024];
    const int t = threadIdx.x;
    const int CH = 49;                               // 1024*49 >= 50000
    int start = t * CH;
    int end   = start + CH; if (end > N_NODES) end = N_NODES;
    int sum = 0;
    for (int i = start; i < end; i++) sum += deg[i];
    sp[t] = sum;
    __syncthreads();
    for (int d = 1; d < 1024; d <<= 1) {
        int v = (t >= d) ? sp[t - d] : 0;
        __syncthreads();
        sp[t] += v;
        __syncthreads();
    }
    int run = (t == 0) ? 0 : sp[t - 1];
    for (int i = start; i < end; i++) { off[i] = run; cur[i] = run; run += deg[i]; }
    if (start < N_NODES && end == N_NODES) off[N_NODES] = run;
}

__global__ void k_scatteridx(const int* __restrict__ ei,
                             int* __restrict__ cin, int* __restrict__ cout_,
                             int* __restrict__ isrc, int* __restrict__ ieid,
                             int* __restrict__ odst) {
    int e = blockIdx.x * 256 + threadIdx.x;
    if (e >= N_EDGES) return;
    int s = ei[e];
    int d = ei[N_EDGES + e];
    int p1 = atomicAdd(&cin[d], 1);
    isrc[p1] = s; ieid[p1] = e;
    int p2 = atomicAdd(&cout_[s], 1);
    odst[p2] = d;
}

__global__ void k_f2h(const float* __restrict__ s, __half* __restrict__ d, int n, int ntot) {
    int i = blockIdx.x * blockDim.x + threadIdx.x;
    if (i < ntot) d[i] = (i < n) ? __float2half(s[i]) : __half(0.f);
}

// Wc = Wg @ Wo  (fp32 accumulate, round once to half)
__global__ void k_wc(const float* __restrict__ Wg, const float* __restrict__ Wo,
                     __half* __restrict__ Wch) {
    int i = blockIdx.x * blockDim.x + threadIdx.x;
    int r = i >> 7, c = i & 127;
    float s = 0.f;
#pragma unroll 8
    for (int k = 0; k < 128; k++) s += Wg[r * 128 + k] * Wo[k * 128 + c];
    Wch[i] = __float2half(s);
}

__global__ void k_bgwo(const float* __restrict__ bg, const float* __restrict__ Wo,
                       float* __restrict__ bgwo) {
    int c = threadIdx.x;
    float s = 0.f;
#pragma unroll 8
    for (int k = 0; k < 128; k++) s += bg[k] * Wo[k * 128 + c];
    bgwo[c] = s;
}

// ---------------- [128rows,128]@[128,128] GEMM, B staged in shared ---------
template <bool HALF_OUT>
__global__ void k_gemm(const __half* __restrict__ A, const __half* __restrict__ B,
                       const float* __restrict__ bias, void* __restrict__ C) {
    extern __shared__ char smem[];
    __half* sB = reinterpret_cast<__half*>(smem);    // 128 x 136 halves
    float*  sT = reinterpret_cast<float*>(smem);     // reused for staging out

    const int tid  = threadIdx.x;
    const int warp = tid >> 5;
    const int lane = tid & 31;

#pragma unroll
    for (int j = 0; j < 32; j++) {                   // 8192 half2
        int idx = j * 256 + tid;
        int row = idx >> 6, c2 = idx & 63;
        *reinterpret_cast<__half2*>(sB + row * 136 + c2 * 2) =
            *reinterpret_cast<const __half2*>(B + row * 128 + c2 * 2);
    }
    __syncthreads();

    const int row0 = blockIdx.x * 128 + warp * 16;
    wmma::fragment<wmma::accumulator, 16, 16, 16, float> acc[8];
#pragma unroll
    for (int n = 0; n < 8; n++) wmma::fill_fragment(acc[n], 0.f);

#pragma unroll
    for (int k = 0; k < 8; k++) {
        wmma::fragment<wmma::matrix_a, 16, 16, 16, __half, wmma::row_major> a;
        wmma::load_matrix_sync(a, A + (size_t)row0 * 128 + k * 16, 128);
#pragma unroll
        for (int n = 0; n < 8; n++) {
            wmma::fragment<wmma::matrix_b, 16, 16, 16, __half, wmma::row_major> b;
            wmma::load_matrix_sync(b, sB + (k * 16) * 136 + n * 16, 136);
            wmma::mma_sync(acc[n], a, b, acc[n]);
        }
    }
    __syncthreads();                                 // done with sB

    float* my = sT + warp * 16 * 132;
#pragma unroll
    for (int n = 0; n < 8; n++)
        wmma::store_matrix_sync(my + n * 16, acc[n], 132, wmma::mem_row_major);
    __syncwarp();

    float4 bv = make_float4(0.f, 0.f, 0.f, 0.f);
    if (bias) bv = *reinterpret_cast<const float4*>(bias + lane * 4);

#pragma unroll
    for (int r = 0; r < 16; r++) {
        float4 v = *reinterpret_cast<const float4*>(my + r * 132 + lane * 4);
        v.x += bv.x; v.y += bv.y; v.z += bv.z; v.w += bv.w;
        if (HALF_OUT) {
            __half2 h0 = __floats2half2_rn(v.x, v.y);
            __half2 h1 = __floats2half2_rn(v.z, v.w);
            uint2 u = make_uint2(*(unsigned*)&h0, *(unsigned*)&h1);
            *reinterpret_cast<uint2*>((__half*)C + (size_t)(row0 + r) * 128 + lane * 4) = u;
        } else {
            *reinterpret_cast<float4*>((float*)C + (size_t)(row0 + r) * 128 + lane * 4) = v;
        }
    }
}

// ---------------- eaW[e] = half(ea[e] @ We2): SEQUENTIAL stream ------------
__global__ void k_eaw(const float* __restrict__ ea, const __half* __restrict__ W2,
                      __half* __restrict__ eaw) {
    extern __shared__ char smem[];
    __half* sA = reinterpret_cast<__half*>(smem);            // 128 x 136
    __half* sB = reinterpret_cast<__half*>(smem + 34816);    // 128 x 136
    float*  sT = reinterpret_cast<float*>(smem);             // reused

    const int tid  = threadIdx.x;
    const int warp = tid >> 5;
    const size_t e0 = (size_t)blockIdx.x * 128;

#pragma unroll
    for (int j = 0; j < 16; j++) {                   // stream A tile (sequential)
        int idx = j * 256 + tid;
        int row = idx >> 5, c4 = idx & 31;
        float4 v = *reinterpret_cast<const float4*>(ea + (e0 + row) * 128 + c4 * 4);
        *reinterpret_cast<__half2*>(sA + row * 136 + c4 * 4)     = __floats2half2_rn(v.x, v.y);
        *reinterpret_cast<__half2*>(sA + row * 136 + c4 * 4 + 2) = __floats2half2_rn(v.z, v.w);
    }
#pragma unroll
    for (int j = 0; j < 32; j++) {                   // stage W2
        int idx = j * 256 + tid;
        int row = idx >> 6, c2 = idx & 63;
        *reinterpret_cast<__half2*>(sB + row * 136 + c2 * 2) =
            *reinterpret_cast<const __half2*>(W2 + row * 128 + c2 * 2);
    }
    __syncthreads();

    wmma::fragment<wmma::accumulator, 16, 16, 16, float> acc[8];
#pragma unroll
    for (int n = 0; n < 8; n++) wmma::fill_fragment(acc[n], 0.f);

#pragma unroll
    for (int k = 0; k < 8; k++) {
        wmma::fragment<wmma::matrix_a, 16, 16, 16, __half, wmma::row_major> a;
        wmma::load_matrix_sync(a, sA + warp * 16 * 136 + k * 16, 136);
#pragma unroll
        for (int n = 0; n < 8; n++) {
            wmma::fragment<wmma::matrix_b, 16, 16, 16, __half, wmma::row_major> b;
            wmma::load_matrix_sync(b, sB + (k * 16) * 136 + n * 16, 136);
            wmma::mma_sync(acc[n], a, b, acc[n]);
        }
    }
    __syncthreads();                                 // done reading sA/sB

    float* my = sT + warp * 16 * 132;
#pragma unroll
    for (int n = 0; n < 8; n++)
        wmma::store_matrix_sync(my + n * 16, acc[n], 132, wmma::mem_row_major);
    __syncthreads();                                 // write loop spans all warps

#pragma unroll
    for (int j = 0; j < 32; j++) {                   // 8192 half2 out, sequential
        int idx = j * 256 + tid;
        int row = idx >> 6, c2 = idx & 63;
        float x0 = sT[row * 132 + c2 * 2];
        float x1 = sT[row * 132 + c2 * 2 + 1];
        *reinterpret_cast<__half2*>(eaw + (e0 + row) * 128 + c2 * 2) = __floats2half2_rn(x0, x1);
    }
}

// ---------------- aggregation: aggh[n] = half(sum_in silu(xd[n]+be+xs[s]+eaW[e]))
__device__ __forceinline__ float silu1(float v) { return v / (1.f + __expf(-v)); }

__device__ __forceinline__ float4 ldh4(const __half* p) {   // 4 halves via one 8B LDG
    uint2 u = *reinterpret_cast<const uint2*>(p);
    __half2 h0 = *reinterpret_cast<__half2*>(&u.x);
    __half2 h1 = *reinterpret_cast<__half2*>(&u.y);
    float2 f0 = __half22float2(h0);
    float2 f1 = __half22float2(h1);
    return make_float4(f0.x, f0.y, f1.x, f1.y);
}

__global__ void k_agg(const int* __restrict__ off, const int* __restrict__ csrs,
                      const int* __restrict__ csre,
                      const float* __restrict__ xd, const __half* __restrict__ xsh,
                      const __half* __restrict__ eaw, const float* __restrict__ be,
                      __half* __restrict__ aggh) {
    const int w    = (blockIdx.x * 256 + threadIdx.x) >> 5;    // node id
    const int lane = threadIdx.x & 31;
    if (w >= N_NODES) return;

    float4 base = *reinterpret_cast<const float4*>(xd + (size_t)w * 128 + lane * 4);
    float4 bb   = *reinterpret_cast<const float4*>(be + lane * 4);
    base.x += bb.x; base.y += bb.y; base.z += bb.z; base.w += bb.w;

    float4 acc = make_float4(0.f, 0.f, 0.f, 0.f);
    const int beg = off[w], end = off[w + 1];
#pragma unroll 4
    for (int i = beg; i < end; i++) {
        int s = csrs[i];
        int e = csre[i];
        float4 v = ldh4(xsh + (size_t)s * 128 + lane * 4);
        float4 t = ldh4(eaw + (size_t)e * 128 + lane * 4);
        acc.x += silu1(base.x + v.x + t.x);
        acc.y += silu1(base.y + v.y + t.y);
        acc.z += silu1(base.z + v.z + t.z);
        acc.w += silu1(base.w + v.w + t.w);
    }
    __half2 h0 = __floats2half2_rn(acc.x, acc.y);
    __half2 h1 = __floats2half2_rn(acc.z, acc.w);
    uint2 u = make_uint2(*(unsigned*)&h0, *(unsigned*)&h1);
    *reinterpret_cast<uint2*>(aggh + (size_t)w * 128 + lane * 4) = u;
}

// ---------------- output: out[n] = bo + sum_out hW[dst] ---------------------
__global__ void k_out(const int* __restrict__ off, const int* __restrict__ odst,
                      const __half* __restrict__ hWh, const float* __restrict__ bo,
                      float* __restrict__ out) {
    const int w    = (blockIdx.x * 256 + threadIdx.x) >> 5;
    const int lane = threadIdx.x & 31;
    if (w >= N_NODES) return;

    float4 acc = *reinterpret_cast<const float4*>(bo + lane * 4);
    const int beg = off[w], end = off[w + 1];
#pragma unroll 4
    for (int i = beg; i < end; i++) {
        int d = odst[i];
        float4 v = ldh4(hWh + (size_t)d * 128 + lane * 4);
        acc.x += v.x; acc.y += v.y; acc.z += v.z; acc.w += v.w;
    }
    *reinterpret_cast<float4*>(out + (size_t)w * 128 + lane * 4) = acc;
}

// ---------------- launch ----------------------------------------------------
extern "C" void kernel_launch(void* const* d_in, const int* in_sizes, int n_in,
                              void* d_out, int out_size) {
    const float* x  = (const float*)d_in[0];
    const int*   ei = (const int*)d_in[1];     // int32 (JAX x64 disabled)
    const float* ea = (const float*)d_in[2];
    const float* We = (const float*)d_in[3];
    const float* be = (const float*)d_in[4];
    const float* Wg = (const float*)d_in[5];
    const float* bg = (const float*)d_in[6];
    // d_in[7]=Wa, d_in[8]=ba: dead (softmax over size-1 axis == 1)
    const float* Wo = (const float*)d_in[9];
    const float* bo = (const float*)d_in[10];
    float*       out = (float*)d_out;

    void *p;
    __half *xh, *xsh, *aggh, *hWh, *eawh, *Weh, *Wch;
    float *xd, *bgwo;
    int *din, *dout_, *oin, *oout, *cin, *cout_, *isrc, *ieid, *odst;
    cudaGetSymbolAddress(&p, g_xh);          xh    = (__half*)p;
    cudaGetSymbolAddress(&p, g_xd);          xd    = (float*)p;
    cudaGetSymbolAddress(&p, g_xsh);         xsh   = (__half*)p;
    cudaGetSymbolAddress(&p, g_aggh);        aggh  = (__half*)p;
    cudaGetSymbolAddress(&p, g_hWh);         hWh   = (__half*)p;
    cudaGetSymbolAddress(&p, g_eawh);        eawh  = (__half*)p;
    cudaGetSymbolAddress(&p, g_Weh);         Weh   = (__half*)p;
    cudaGetSymbolAddress(&p, g_Wch);         Wch   = (__half*)p;
    cudaGetSymbolAddress(&p, g_bgwo);        bgwo  = (float*)p;
    cudaGetSymbolAddress(&p, g_deg_in);      din   = (int*)p;
    cudaGetSymbolAddress(&p, g_deg_out);     dout_ = (int*)p;
    cudaGetSymbolAddress(&p, g_off_in);      oin   = (int*)p;
    cudaGetSymbolAddress(&p, g_off_out);     oout  = (int*)p;
    cudaGetSymbolAddress(&p, g_cur_in);      cin   = (int*)p;
    cudaGetSymbolAddress(&p, g_cur_out);     cout_ = (int*)p;
    cudaGetSymbolAddress(&p, g_csr_in_src);  isrc  = (int*)p;
    cudaGetSymbolAddress(&p, g_csr_in_eid);  ieid  = (int*)p;
    cudaGetSymbolAddress(&p, g_csr_out_dst); odst  = (int*)p;

    const size_t gemm_shmem = 67584;
    const size_t eaw_shmem  = 69632;
    cudaFuncSetAttribute(k_gemm<false>, cudaFuncAttributeMaxDynamicSharedMemorySize, (int)gemm_shmem);
    cudaFuncSetAttribute(k_gemm<true>,  cudaFuncAttributeMaxDynamicSharedMemorySize, (int)gemm_shmem);
    cudaFuncSetAttribute(k_eaw,         cudaFuncAttributeMaxDynamicSharedMemorySize, (int)eaw_shmem);

    const int NH  = N_NODES * HDIM;
    const int NHP = NPAD * HDIM;
    const int gblocks = NPAD / 128;           // 391
    const int eblocks = N_EDGES / 128;        // 6250
    const int nwarp_blocks = (N_NODES * 32 + 255) / 256;   // 6250

    // 1-5: CSR build + weight convert
    k_zerodeg<<<(N_NODES + 255) / 256, 256>>>(din, dout_);                    // 1
    k_hist<<<(N_EDGES + 255) / 256, 256>>>(ei, din, dout_);                   // 2
    k_scan2<<<2, 1024>>>(din, oin, cin, dout_, oout, cout_);                  // 3
    k_scatteridx<<<(N_EDGES + 255) / 256, 256>>>(ei, cin, cout_, isrc, ieid, odst); // 4
    k_f2h<<<(3 * WSZ + 255) / 256, 256>>>(We, Weh, 3 * WSZ, 3 * WSZ);         // 5

    // 6: sequential edge GEMM (profiled by ncu)
    k_eaw<<<eblocks, 256, eaw_shmem>>>(ea, Weh + 2 * WSZ, eawh);              // 6

    // node-side prep
    k_f2h<<<(NHP + 255) / 256, 256>>>(x, xh, NH, NHP);                        // 7
    k_wc<<<64, 256>>>(Wg, Wo, Wch);                                           // 8
    k_bgwo<<<1, 128>>>(bg, Wo, bgwo);                                         // 9
    k_gemm<false><<<gblocks, 256, gemm_shmem>>>(xh, Weh,       nullptr, xd);  // 10
    k_gemm<true ><<<gblocks, 256, gemm_shmem>>>(xh, Weh + WSZ, nullptr, xsh); // 11

    // atomic-free aggregation (random 256B eaW gathers, 8B xs gathers)
    k_agg<<<nwarp_blocks, 256>>>(oin, isrc, ieid, xd, xsh, eawh, be, aggh);   // 12

    // hW = agg @ (Wg@Wo) + bg@Wo, half out
    k_gemm<true><<<gblocks, 256, gemm_shmem>>>(aggh, Wch, bgwo, hWh);         // 13

    // out[n] = bo + sum hW[dst] over out-edges
    k_out<<<nwarp_blocks, 256>>>(oout, odst, hWh, bo, out);                   // 14
}

// round 9
// speedup vs baseline: 1.7527x; 1.2424x over previous
#include <cuda_runtime.h>
#include <cuda_fp16.h>
#include <mma.h>

using namespace nvcuda;

#define N_NODES 50000
#define N_EDGES 800000
#define HDIM    128
#define NPAD    50048           // ceil(N/128)*128
#define WSZ     (HDIM * HDIM)

// ---------------- scratch (device globals; no allocation allowed) ----------
__device__ float  g_xd   [NPAD * HDIM];              // x @ We0 + be (fp32)
__device__ __half g_xsh  [NPAD * HDIM];              // half(x @ We1)
__device__ __half g_aggh [NPAD * HDIM];              // half(segment_sum)
__device__ __half g_hWh  [NPAD * HDIM];              // half(agg @ Wc + bgwo)
__device__ __half g_eawh [(size_t)N_EDGES * HDIM];   // half(ea @ We2), EDGE-ID order
__device__ __half g_Weh  [3 * WSZ];
__device__ __half g_Wch  [WSZ];                      // half(Wg@Wo)
__device__ float  g_bgwo [HDIM];                     // bg@Wo
// CSR machinery
__device__ int  g_deg_in [N_NODES];
__device__ int  g_deg_out[N_NODES];
__device__ int  g_off_in [N_NODES + 1];
__device__ int  g_off_out[N_NODES + 1];
__device__ int  g_cur_in [N_NODES];
__device__ int  g_cur_out[N_NODES];
__device__ int2 g_csr_in_se[N_EDGES];   // in-CSR: (source node, edge id)
__device__ int  g_csr_out_dst[N_EDGES]; // out-CSR: dest node per out-edge

// ---------------- small utility kernels ------------------------------------
__global__ void k_zerodeg(int* __restrict__ din, int* __restrict__ dout) {
    int i = blockIdx.x * blockDim.x + threadIdx.x;
    if (i < N_NODES) { din[i] = 0; dout[i] = 0; }
}

__global__ void k_hist(const int* __restrict__ ei, int* __restrict__ din, int* __restrict__ dout) {
    int e = blockIdx.x * 256 + threadIdx.x;
    if (e >= N_EDGES) return;
    atomicAdd(&dout[ei[e]], 1);            // src
    atomicAdd(&din[ei[N_EDGES + e]], 1);   // dst
}

// 2-block kernel: block 0 scans in-degrees, block 1 scans out-degrees
__global__ void k_scan2(const int* __restrict__ din, int* __restrict__ oin, int* __restrict__ cin,
                        const int* __restrict__ dout, int* __restrict__ oout, int* __restrict__ cout_) {
    const int* deg = blockIdx.x ? dout : din;
    int* off = blockIdx.x ? oout : oin;
    int* cur = blockIdx.x ? cout_ : cin;

    __shared__ int sp[1024];
    const int t = threadIdx.x;
    const int CH = 49;                               // 1024*49 >= 50000
    int start = t * CH;
    int end   = start + CH; if (end > N_NODES) end = N_NODES;
    int sum = 0;
    for (int i = start; i < end; i++) sum += deg[i];
    sp[t] = sum;
    __syncthreads();
    for (int d = 1; d < 1024; d <<= 1) {
        int v = (t >= d) ? sp[t - d] : 0;
        __syncthreads();
        sp[t] += v;
        __syncthreads();
    }
    int run = (t == 0) ? 0 : sp[t - 1];
    for (int i = start; i < end; i++) { off[i] = run; cur[i] = run; run += deg[i]; }
    if (start < N_NODES && end == N_NODES) off[N_NODES] = run;
}

__global__ void k_scatteridx(const int* __restrict__ ei,
                             int* __restrict__ cin, int* __restrict__ cout_,
                             int2* __restrict__ ise, int* __restrict__ odst) {
    int e = blockIdx.x * 256 + threadIdx.x;
    if (e >= N_EDGES) return;
    int s = ei[e];
    int d = ei[N_EDGES + e];
    int p1 = atomicAdd(&cin[d], 1);
    ise[p1] = make_int2(s, e);
    int p2 = atomicAdd(&cout_[s], 1);
    odst[p2] = d;
}

__global__ void k_f2h(const float* __restrict__ s, __half* __restrict__ d, int n) {
    int i = blockIdx.x * blockDim.x + threadIdx.x;
    if (i < n) d[i] = __float2half(s[i]);
}

// Wc = Wg @ Wo  (fp32 accumulate, round once to half)
__global__ void k_wc(const float* __restrict__ Wg, const float* __restrict__ Wo,
                     __half* __restrict__ Wch) {
    int i = blockIdx.x * blockDim.x + threadIdx.x;
    int r = i >> 7, c = i & 127;
    float s = 0.f;
#pragma unroll 8
    for (int k = 0; k < 128; k++) s += Wg[r * 128 + k] * Wo[k * 128 + c];
    Wch[i] = __float2half(s);
}

__global__ void k_bgwo(const float* __restrict__ bg, const float* __restrict__ Wo,
                       float* __restrict__ bgwo) {
    int c = threadIdx.x;
    float s = 0.f;
#pragma unroll 8
    for (int k = 0; k < 128; k++) s += bg[k] * Wo[k * 128 + c];
    bgwo[c] = s;
}

// ---------------- unified [M,128]@[128,128] GEMM ----------------------------
// A: fp32 or half, staged (+converted) in smem. B staged in smem.
// Out: fp32 or half, optional fp32 bias. A loads guarded by m_rows.
template <bool A_FP32, bool HALF_OUT>
__global__ void k_mm(const void* __restrict__ Av, const __half* __restrict__ B,
                     const float* __restrict__ bias, void* __restrict__ C, int m_rows) {
    extern __shared__ char smem[];
    __half* sA = reinterpret_cast<__half*>(smem);            // 128 x 136 halves
    __half* sB = reinterpret_cast<__half*>(smem + 34816);    // 128 x 136 halves
    float*  sT = reinterpret_cast<float*>(smem);             // reused staging

    const int tid  = threadIdx.x;
    const int warp = tid >> 5;
    const int lane = tid & 31;
    const size_t r0 = (size_t)blockIdx.x * 128;

    if (A_FP32) {
        const float* A = (const float*)Av;
#pragma unroll
        for (int j = 0; j < 16; j++) {               // 4096 float4
            int idx = j * 256 + tid;
            int row = idx >> 5, c4 = idx & 31;
            float4 v = make_float4(0.f, 0.f, 0.f, 0.f);
            if ((int)(r0 + row) < m_rows)
                v = *reinterpret_cast<const float4*>(A + (r0 + row) * 128 + c4 * 4);
            *reinterpret_cast<__half2*>(sA + row * 136 + c4 * 4)     = __floats2half2_rn(v.x, v.y);
            *reinterpret_cast<__half2*>(sA + row * 136 + c4 * 4 + 2) = __floats2half2_rn(v.z, v.w);
        }
    } else {
        const __half* A = (const __half*)Av;
#pragma unroll
        for (int j = 0; j < 32; j++) {               // 8192 half2
            int idx = j * 256 + tid;
            int row = idx >> 6, c2 = idx & 63;
            __half2 v = __floats2half2_rn(0.f, 0.f);
            if ((int)(r0 + row) < m_rows)
                v = *reinterpret_cast<const __half2*>(A + (r0 + row) * 128 + c2 * 2);
            *reinterpret_cast<__half2*>(sA + row * 136 + c2 * 2) = v;
        }
    }
#pragma unroll
    for (int j = 0; j < 32; j++) {                   // stage B
        int idx = j * 256 + tid;
        int row = idx >> 6, c2 = idx & 63;
        *reinterpret_cast<__half2*>(sB + row * 136 + c2 * 2) =
            *reinterpret_cast<const __half2*>(B + row * 128 + c2 * 2);
    }
    __syncthreads();

    wmma::fragment<wmma::accumulator, 16, 16, 16, float> acc[8];
#pragma unroll
    for (int n = 0; n < 8; n++) wmma::fill_fragment(acc[n], 0.f);

#pragma unroll
    for (int k = 0; k < 8; k++) {
        wmma::fragment<wmma::matrix_a, 16, 16, 16, __half, wmma::row_major> a;
        wmma::load_matrix_sync(a, sA + warp * 16 * 136 + k * 16, 136);
#pragma unroll
        for (int n = 0; n < 8; n++) {
            wmma::fragment<wmma::matrix_b, 16, 16, 16, __half, wmma::row_major> b;
            wmma::load_matrix_sync(b, sB + (k * 16) * 136 + n * 16, 136);
            wmma::mma_sync(acc[n], a, b, acc[n]);
        }
    }
    __syncthreads();                                 // done with sA/sB

    float* my = sT + warp * 16 * 132;
#pragma unroll
    for (int n = 0; n < 8; n++)
        wmma::store_matrix_sync(my + n * 16, acc[n], 132, wmma::mem_row_major);
    __syncwarp();                                    // each warp reads its own rows

    float4 bv = make_float4(0.f, 0.f, 0.f, 0.f);
    if (bias) bv = *reinterpret_cast<const float4*>(bias + lane * 4);

    const size_t row0 = r0 + warp * 16;
#pragma unroll
    for (int r = 0; r < 16; r++) {
        float4 v = *reinterpret_cast<const float4*>(my + r * 132 + lane * 4);
        v.x += bv.x; v.y += bv.y; v.z += bv.z; v.w += bv.w;
        if (HALF_OUT) {
            __half2 h0 = __floats2half2_rn(v.x, v.y);
            __half2 h1 = __floats2half2_rn(v.z, v.w);
            uint2 u = make_uint2(*(unsigned*)&h0, *(unsigned*)&h1);
            *reinterpret_cast<uint2*>((__half*)C + (row0 + r) * 128 + lane * 4) = u;
        } else {
            *reinterpret_cast<float4*>((float*)C + (row0 + r) * 128 + lane * 4) = v;
        }
    }
}

// ---------------- aggregation: aggh[n] = half(sum_in silu(xd[n] + xs[s] + eaW[e]))
__device__ __forceinline__ float silu1(float v) { return v / (1.f + __expf(-v)); }

__device__ __forceinline__ float4 ldh4(const __half* p) {   // 4 halves via one 8B LDG
    uint2 u = *reinterpret_cast<const uint2*>(p);
    __half2 h0 = *reinterpret_cast<__half2*>(&u.x);
    __half2 h1 = *reinterpret_cast<__half2*>(&u.y);
    float2 f0 = __half22float2(h0);
    float2 f1 = __half22float2(h1);
    return make_float4(f0.x, f0.y, f1.x, f1.y);
}

__global__ void k_agg(const int* __restrict__ off, const int2* __restrict__ se,
                      const float* __restrict__ xd, const __half* __restrict__ xsh,
                      const __half* __restrict__ eaw, __half* __restrict__ aggh) {
    const int w    = (blockIdx.x * 256 + threadIdx.x) >> 5;    // node id
    const int lane = threadIdx.x & 31;
    if (w >= N_NODES) return;

    // base = xd[w] (be already folded in via GEMM bias)
    float4 base = *reinterpret_cast<const float4*>(xd + (size_t)w * 128 + lane * 4);

    float4 acc = make_float4(0.f, 0.f, 0.f, 0.f);
    const int beg = off[w], end = off[w + 1];
#pragma unroll 4
    for (int i = beg; i < end; i++) {
        int2 p = se[i];                              // (src, eid) one 8B broadcast load
        float4 v = ldh4(xsh + (size_t)p.x * 128 + lane * 4);
        float4 t = ldh4(eaw + (size_t)p.y * 128 + lane * 4);
        acc.x += silu1(base.x + v.x + t.x);
        acc.y += silu1(base.y + v.y + t.y);
        acc.z += silu1(base.z + v.z + t.z);
        acc.w += silu1(base.w + v.w + t.w);
    }
    __half2 h0 = __floats2half2_rn(acc.x, acc.y);
    __half2 h1 = __floats2half2_rn(acc.z, acc.w);
    uint2 u = make_uint2(*(unsigned*)&h0, *(unsigned*)&h1);
    *reinterpret_cast<uint2*>(aggh + (size_t)w * 128 + lane * 4) = u;
}

// ---------------- output: out[n] = bo + sum_out hW[dst] ---------------------
__global__ void k_out(const int* __restrict__ off, const int* __restrict__ odst,
                      const __half* __restrict__ hWh, const float* __restrict__ bo,
                      float* __restrict__ out) {
    const int w    = (blockIdx.x * 256 + threadIdx.x) >> 5;
    const int lane = threadIdx.x & 31;
    if (w >= N_NODES) return;

    float4 acc = *reinterpret_cast<const float4*>(bo + lane * 4);
    const int beg = off[w], end = off[w + 1];
#pragma unroll 4
    for (int i = beg; i < end; i++) {
        int d = odst[i];
        float4 v = ldh4(hWh + (size_t)d * 128 + lane * 4);
        acc.x += v.x; acc.y += v.y; acc.z += v.z; acc.w += v.w;
    }
    *reinterpret_cast<float4*>(out + (size_t)w * 128 + lane * 4) = acc;
}

// ---------------- launch ----------------------------------------------------
extern "C" void kernel_launch(void* const* d_in, const int* in_sizes, int n_in,
                              void* d_out, int out_size) {
    const float* x  = (const float*)d_in[0];
    const int*   ei = (const int*)d_in[1];     // int32 (JAX x64 disabled)
    const float* ea = (const float*)d_in[2];
    const float* We = (const float*)d_in[3];
    const float* be = (const float*)d_in[4];
    const float* Wg = (const float*)d_in[5];
    const float* bg = (const float*)d_in[6];
    // d_in[7]=Wa, d_in[8]=ba: dead (softmax over size-1 axis == 1)
    const float* Wo = (const float*)d_in[9];
    const float* bo = (const float*)d_in[10];
    float*       out = (float*)d_out;

    void *p;
    __half *xsh, *aggh, *hWh, *eawh, *Weh, *Wch;
    float *xd, *bgwo;
    int *din, *dout_, *oin, *oout, *cin, *cout_, *odst;
    int2 *ise;
    cudaGetSymbolAddress(&p, g_xd);          xd    = (float*)p;
    cudaGetSymbolAddress(&p, g_xsh);         xsh   = (__half*)p;
    cudaGetSymbolAddress(&p, g_aggh);        aggh  = (__half*)p;
    cudaGetSymbolAddress(&p, g_hWh);         hWh   = (__half*)p;
    cudaGetSymbolAddress(&p, g_eawh);        eawh  = (__half*)p;
    cudaGetSymbolAddress(&p, g_Weh);         Weh   = (__half*)p;
    cudaGetSymbolAddress(&p, g_Wch);         Wch   = (__half*)p;
    cudaGetSymbolAddress(&p, g_bgwo);        bgwo  = (float*)p;
    cudaGetSymbolAddress(&p, g_deg_in);      din   = (int*)p;
    cudaGetSymbolAddress(&p, g_deg_out);     dout_ = (int*)p;
    cudaGetSymbolAddress(&p, g_off_in);      oin   = (int*)p;
    cudaGetSymbolAddress(&p, g_off_out);     oout  = (int*)p;
    cudaGetSymbolAddress(&p, g_cur_in);      cin   = (int*)p;
    cudaGetSymbolAddress(&p, g_cur_out);     cout_ = (int*)p;
    cudaGetSymbolAddress(&p, g_csr_in_se);   ise   = (int2*)p;
    cudaGetSymbolAddress(&p, g_csr_out_dst); odst  = (int*)p;

    const size_t mm_shmem = 69632;            // sA + sB (sT reuses the region)
    cudaFuncSetAttribute(k_mm<true,  false>, cudaFuncAttributeMaxDynamicSharedMemorySize, (int)mm_shmem);
    cudaFuncSetAttribute(k_mm<true,  true >, cudaFuncAttributeMaxDynamicSharedMemorySize, (int)mm_shmem);
    cudaFuncSetAttribute(k_mm<false, true >, cudaFuncAttributeMaxDynamicSharedMemorySize, (int)mm_shmem);

    const int gblocks = NPAD / 128;           // 391
    const int eblocks = N_EDGES / 128;        // 6250
    const int nwarp_blocks = (N_NODES * 32 + 255) / 256;   // 6250

    // CSR build + weight prep
    k_zerodeg<<<(N_NODES + 255) / 256, 256>>>(din, dout_);                          // 1
    k_hist<<<(N_EDGES + 255) / 256, 256>>>(ei, din, dout_);                         // 2
    k_scan2<<<2, 1024>>>(din, oin, cin, dout_, oout, cout_);                        // 3
    k_scatteridx<<<(N_EDGES + 255) / 256, 256>>>(ei, cin, cout_, ise, odst);        // 4
    k_f2h<<<(3 * WSZ + 255) / 256, 256>>>(We, Weh, 3 * WSZ);                        // 5

    // sequential edge GEMM: eaW = half(ea @ We2)
    k_mm<true, true><<<eblocks, 256, mm_shmem>>>(ea, Weh + 2 * WSZ, nullptr, eawh, N_EDGES); // 6

    // weight folds + node precomputes (fp32 x read directly, converted in-kernel)
    k_wc<<<64, 256>>>(Wg, Wo, Wch);                                                 // 7
    k_bgwo<<<1, 128>>>(bg, Wo, bgwo);                                               // 8
    k_mm<true, false><<<gblocks, 256, mm_shmem>>>(x, Weh,       be,      xd,  N_NODES); // 9 (be folded)
    k_mm<true, true ><<<gblocks, 256, mm_shmem>>>(x, Weh + WSZ, nullptr, xsh, N_NODES); // 10

    // atomic-free aggregation
    k_agg<<<nwarp_blocks, 256>>>(oin, ise, xd, xsh, eawh, aggh);                    // 11

    // hW = agg @ (Wg@Wo) + bg@Wo
    k_mm<false, true><<<gblocks, 256, mm_shmem>>>(aggh, Wch, bgwo, hWh, NPAD);      // 12

    // out[n] = bo + sum hW[dst] over out-edges
    k_out<<<nwarp_blocks, 256>>>(oout, odst, hWh, bo, out);                         // 13
}

// round 10
// speedup vs baseline: 1.8964x; 1.0820x over previous
#include <cuda_runtime.h>
#include <cuda_fp16.h>
#include <mma.h>

using namespace nvcuda;

#define N_NODES 50000
#define N_EDGES 800000
#define HDIM    128
#define NPAD    50048           // ceil(N/128)*128
#define WSZ     (HDIM * HDIM)

// ---------------- scratch (device globals; no allocation allowed) ----------
__device__ float  g_xd   [NPAD * HDIM];              // x @ We0 + be (fp32)
__device__ __half g_xsh  [NPAD * HDIM];              // half(x @ We1)
__device__ __half g_aggh [NPAD * HDIM];              // half(segment_sum)
__device__ __half g_hWh  [NPAD * HDIM];              // half(agg @ Wc + bgwo)
__device__ __half g_eawh [(size_t)N_EDGES * HDIM];   // half(ea@We2 + xs[src]), CSR order
__device__ __half g_Weh  [3 * WSZ];
__device__ __half g_Wch  [WSZ];                      // half(Wg@Wo)
__device__ float  g_bgwo [HDIM];                     // bg@Wo
// CSR machinery
__device__ int  g_deg_in [N_NODES];
__device__ int  g_deg_out[N_NODES];
__device__ int  g_off_in [N_NODES + 1];
__device__ int  g_off_out[N_NODES + 1];
__device__ int  g_cur_in [N_NODES];
__device__ int  g_cur_out[N_NODES];
__device__ int  g_pos2   [N_EDGES];     // edge id -> in-CSR position
__device__ int  g_csr_out_dst[N_EDGES]; // out-CSR: dest node per out-edge

// ---------------- small utility kernels ------------------------------------
__global__ void k_zerodeg(int* __restrict__ din, int* __restrict__ dout) {
    int i = blockIdx.x * blockDim.x + threadIdx.x;
    if (i < N_NODES) { din[i] = 0; dout[i] = 0; }
}

__global__ void k_hist(const int* __restrict__ ei, int* __restrict__ din, int* __restrict__ dout) {
    int e = blockIdx.x * 256 + threadIdx.x;
    if (e >= N_EDGES) return;
    atomicAdd(&dout[ei[e]], 1);            // src
    atomicAdd(&din[ei[N_EDGES + e]], 1);   // dst
}

// 2-block kernel: block 0 scans in-degrees, block 1 scans out-degrees
__global__ void k_scan2(const int* __restrict__ din, int* __restrict__ oin, int* __restrict__ cin,
                        const int* __restrict__ dout, int* __restrict__ oout, int* __restrict__ cout_) {
    const int* deg = blockIdx.x ? dout : din;
    int* off = blockIdx.x ? oout : oin;
    int* cur = blockIdx.x ? cout_ : cin;

    __shared__ int sp[1024];
    const int t = threadIdx.x;
    const int CH = 49;                               // 1024*49 >= 50000
    int start = t * CH;
    int end   = start + CH; if (end > N_NODES) end = N_NODES;
    int sum = 0;
    for (int i = start; i < end; i++) sum += deg[i];
    sp[t] = sum;
    __syncthreads();
    for (int d = 1; d < 1024; d <<= 1) {
        int v = (t >= d) ? sp[t - d] : 0;
        __syncthreads();
        sp[t] += v;
        __syncthreads();
    }
    int run = (t == 0) ? 0 : sp[t - 1];
    for (int i = start; i < end; i++) { off[i] = run; cur[i] = run; run += deg[i]; }
    if (start < N_NODES && end == N_NODES) off[N_NODES] = run;
}

__global__ void k_scatteridx(const int* __restrict__ ei,
                             int* __restrict__ cin, int* __restrict__ cout_,
                             int* __restrict__ pos2, int* __restrict__ odst) {
    int e = blockIdx.x * 256 + threadIdx.x;
    if (e >= N_EDGES) return;
    int s = ei[e];
    int d = ei[N_EDGES + e];
    int p1 = atomicAdd(&cin[d], 1);
    pos2[e] = p1;                          // eid -> csr position (sequential write)
    int p2 = atomicAdd(&cout_[s], 1);
    odst[p2] = d;
}

__global__ void k_f2h(const float* __restrict__ s, __half* __restrict__ d, int n) {
    int i = blockIdx.x * blockDim.x + threadIdx.x;
    if (i < n) d[i] = __float2half(s[i]);
}

// Wc = Wg @ Wo  (fp32 accumulate, round once to half)
__global__ void k_wc(const float* __restrict__ Wg, const float* __restrict__ Wo,
                     __half* __restrict__ Wch) {
    int i = blockIdx.x * blockDim.x + threadIdx.x;
    int r = i >> 7, c = i & 127;
    float s = 0.f;
#pragma unroll 8
    for (int k = 0; k < 128; k++) s += Wg[r * 128 + k] * Wo[k * 128 + c];
    Wch[i] = __float2half(s);
}

__global__ void k_bgwo(const float* __restrict__ bg, const float* __restrict__ Wo,
                       float* __restrict__ bgwo) {
    int c = threadIdx.x;
    float s = 0.f;
#pragma unroll 8
    for (int k = 0; k < 128; k++) s += bg[k] * Wo[k * 128 + c];
    bgwo[c] = s;
}

__device__ __forceinline__ float4 ldh4(const __half* p) {   // 4 halves via one 8B LDG
    uint2 u = *reinterpret_cast<const uint2*>(p);
    __half2 h0 = *reinterpret_cast<__half2*>(&u.x);
    __half2 h1 = *reinterpret_cast<__half2*>(&u.y);
    float2 f0 = __half22float2(h0);
    float2 f1 = __half22float2(h1);
    return make_float4(f0.x, f0.y, f1.x, f1.y);
}

// ---------------- unified [M,128]@[128,128] GEMM ----------------------------
template <bool A_FP32, bool HALF_OUT>
__global__ void k_mm(const void* __restrict__ Av, const __half* __restrict__ B,
                     const float* __restrict__ bias, void* __restrict__ C, int m_rows) {
    extern __shared__ char smem[];
    __half* sA = reinterpret_cast<__half*>(smem);            // 128 x 136 halves
    __half* sB = reinterpret_cast<__half*>(smem + 34816);    // 128 x 136 halves
    float*  sT = reinterpret_cast<float*>(smem);             // reused staging

    const int tid  = threadIdx.x;
    const int warp = tid >> 5;
    const int lane = tid & 31;
    const size_t r0 = (size_t)blockIdx.x * 128;

    if (A_FP32) {
        const float* A = (const float*)Av;
#pragma unroll
        for (int j = 0; j < 16; j++) {
            int idx = j * 256 + tid;
            int row = idx >> 5, c4 = idx & 31;
            float4 v = make_float4(0.f, 0.f, 0.f, 0.f);
            if ((int)(r0 + row) < m_rows)
                v = *reinterpret_cast<const float4*>(A + (r0 + row) * 128 + c4 * 4);
            *reinterpret_cast<__half2*>(sA + row * 136 + c4 * 4)     = __floats2half2_rn(v.x, v.y);
            *reinterpret_cast<__half2*>(sA + row * 136 + c4 * 4 + 2) = __floats2half2_rn(v.z, v.w);
        }
    } else {
        const __half* A = (const __half*)Av;
#pragma unroll
        for (int j = 0; j < 32; j++) {
            int idx = j * 256 + tid;
            int row = idx >> 6, c2 = idx & 63;
            __half2 v = __floats2half2_rn(0.f, 0.f);
            if ((int)(r0 + row) < m_rows)
                v = *reinterpret_cast<const __half2*>(A + (r0 + row) * 128 + c2 * 2);
            *reinterpret_cast<__half2*>(sA + row * 136 + c2 * 2) = v;
        }
    }
#pragma unroll
    for (int j = 0; j < 32; j++) {                   // stage B
        int idx = j * 256 + tid;
        int row = idx >> 6, c2 = idx & 63;
        *reinterpret_cast<__half2*>(sB + row * 136 + c2 * 2) =
            *reinterpret_cast<const __half2*>(B + row * 128 + c2 * 2);
    }
    __syncthreads();

    wmma::fragment<wmma::accumulator, 16, 16, 16, float> acc[8];
#pragma unroll
    for (int n = 0; n < 8; n++) wmma::fill_fragment(acc[n], 0.f);

#pragma unroll
    for (int k = 0; k < 8; k++) {
        wmma::fragment<wmma::matrix_a, 16, 16, 16, __half, wmma::row_major> a;
        wmma::load_matrix_sync(a, sA + warp * 16 * 136 + k * 16, 136);
#pragma unroll
        for (int n = 0; n < 8; n++) {
            wmma::fragment<wmma::matrix_b, 16, 16, 16, __half, wmma::row_major> b;
            wmma::load_matrix_sync(b, sB + (k * 16) * 136 + n * 16, 136);
            wmma::mma_sync(acc[n], a, b, acc[n]);
        }
    }
    __syncthreads();                                 // done with sA/sB

    float* my = sT + warp * 16 * 132;
#pragma unroll
    for (int n = 0; n < 8; n++)
        wmma::store_matrix_sync(my + n * 16, acc[n], 132, wmma::mem_row_major);
    __syncwarp();                                    // each warp reads its own rows

    float4 bv = make_float4(0.f, 0.f, 0.f, 0.f);
    if (bias) bv = *reinterpret_cast<const float4*>(bias + lane * 4);

    const size_t row0 = r0 + warp * 16;
#pragma unroll
    for (int r = 0; r < 16; r++) {
        float4 v = *reinterpret_cast<const float4*>(my + r * 132 + lane * 4);
        v.x += bv.x; v.y += bv.y; v.z += bv.z; v.w += bv.w;
        if (HALF_OUT) {
            __half2 h0 = __floats2half2_rn(v.x, v.y);
            __half2 h1 = __floats2half2_rn(v.z, v.w);
            uint2 u = make_uint2(*(unsigned*)&h0, *(unsigned*)&h1);
            *reinterpret_cast<uint2*>((__half*)C + (row0 + r) * 128 + lane * 4) = u;
        } else {
            *reinterpret_cast<float4*>((float*)C + (row0 + r) * 128 + lane * 4) = v;
        }
    }
}

// ------- edge GEMM + xs fold + CSR scatter-write ----------------------------
// eawh[pos2[e]] = half( ea[e]@We2 + xs[src[e]] )   -- sequential ea stream,
// L2-resident xs gathers, scattered 256B row writes (no read-latency exposure).
__global__ void k_eaw(const float* __restrict__ ea, const int* __restrict__ ei,
                      const __half* __restrict__ xsh, const int* __restrict__ pos2,
                      const __half* __restrict__ W2, __half* __restrict__ eaw) {
    extern __shared__ char smem[];
    __half* sA   = reinterpret_cast<__half*>(smem);            // 128 x 136
    __half* sB   = reinterpret_cast<__half*>(smem + 34816);    // 128 x 136
    int*    sSrc = reinterpret_cast<int*>(smem + 69632);       // 128
    int*    sPos = reinterpret_cast<int*>(smem + 70144);       // 128
    float*  sT   = reinterpret_cast<float*>(smem);             // reuses sA/sB

    const int tid  = threadIdx.x;
    const int warp = tid >> 5;
    const size_t e0 = (size_t)blockIdx.x * 128;

    if (tid < 128) {
        sSrc[tid] = ei[e0 + tid];                    // src = edge_index[0]
        sPos[tid] = pos2[e0 + tid];
    }
#pragma unroll
    for (int j = 0; j < 16; j++) {                   // stream A tile (sequential)
        int idx = j * 256 + tid;
        int row = idx >> 5, c4 = idx & 31;
        float4 v = *reinterpret_cast<const float4*>(ea + (e0 + row) * 128 + c4 * 4);
        *reinterpret_cast<__half2*>(sA + row * 136 + c4 * 4)     = __floats2half2_rn(v.x, v.y);
        *reinterpret_cast<__half2*>(sA + row * 136 + c4 * 4 + 2) = __floats2half2_rn(v.z, v.w);
    }
#pragma unroll
    for (int j = 0; j < 32; j++) {                   // stage W2
        int idx = j * 256 + tid;
        int row = idx >> 6, c2 = idx & 63;
        *reinterpret_cast<__half2*>(sB + row * 136 + c2 * 2) =
            *reinterpret_cast<const __half2*>(W2 + row * 128 + c2 * 2);
    }
    __syncthreads();

    wmma::fragment<wmma::accumulator, 16, 16, 16, float> acc[8];
#pragma unroll
    for (int n = 0; n < 8; n++) wmma::fill_fragment(acc[n], 0.f);

#pragma unroll
    for (int k = 0; k < 8; k++) {
        wmma::fragment<wmma::matrix_a, 16, 16, 16, __half, wmma::row_major> a;
        wmma::load_matrix_sync(a, sA + warp * 16 * 136 + k * 16, 136);
#pragma unroll
        for (int n = 0; n < 8; n++) {
            wmma::fragment<wmma::matrix_b, 16, 16, 16, __half, wmma::row_major> b;
            wmma::load_matrix_sync(b, sB + (k * 16) * 136 + n * 16, 136);
            wmma::mma_sync(acc[n], a, b, acc[n]);
        }
    }
    __syncthreads();                                 // done reading sA/sB

    float* my = sT + warp * 16 * 132;
#pragma unroll
    for (int n = 0; n < 8; n++)
        wmma::store_matrix_sync(my + n * 16, acc[n], 132, wmma::mem_row_major);
    __syncthreads();                                 // write loop spans all warps

    // epilogue: + xs[src] (L2 gather), round once, scatter to CSR position.
    // Each warp handles one full 256B output row per iteration.
#pragma unroll
    for (int j = 0; j < 16; j++) {
        int idx = j * 256 + tid;
        int row = idx >> 5, c4 = idx & 31;
        float4 t = *reinterpret_cast<const float4*>(sT + row * 132 + c4 * 4);
        float4 v = ldh4(xsh + (size_t)sSrc[row] * 128 + c4 * 4);
        __half2 h0 = __floats2half2_rn(t.x + v.x, t.y + v.y);
        __half2 h1 = __floats2half2_rn(t.z + v.z, t.w + v.w);
        uint2 u = make_uint2(*(unsigned*)&h0, *(unsigned*)&h1);
        *reinterpret_cast<uint2*>(eaw + (size_t)sPos[row] * 128 + c4 * 4) = u;
    }
}

// ------- aggregation: aggh[n] = half( sum silu(xd[n] + eawh[i]) ), sequential
__device__ __forceinline__ float silu1(float v) { return v / (1.f + __expf(-v)); }

__global__ void k_agg(const int* __restrict__ off,
                      const float* __restrict__ xd, const __half* __restrict__ eaw,
                      __half* __restrict__ aggh) {
    const int w    = (blockIdx.x * 256 + threadIdx.x) >> 5;    // node id
    const int lane = threadIdx.x & 31;
    if (w >= N_NODES) return;

    float4 base = *reinterpret_cast<const float4*>(xd + (size_t)w * 128 + lane * 4);

    float4 acc = make_float4(0.f, 0.f, 0.f, 0.f);
    const int beg = off[w], end = off[w + 1];
#pragma unroll 4
    for (int i = beg; i < end; i++) {                // sequential eaw stream
        float4 t = ldh4(eaw + (size_t)i * 128 + lane * 4);
        acc.x += silu1(base.x + t.x);
        acc.y += silu1(base.y + t.y);
        acc.z += silu1(base.z + t.z);
        acc.w += silu1(base.w + t.w);
    }
    __half2 h0 = __floats2half2_rn(acc.x, acc.y);
    __half2 h1 = __floats2half2_rn(acc.z, acc.w);
    uint2 u = make_uint2(*(unsigned*)&h0, *(unsigned*)&h1);
    *reinterpret_cast<uint2*>(aggh + (size_t)w * 128 + lane * 4) = u;
}

// ---------------- output: out[n] = bo + sum_out hW[dst] ---------------------
__global__ void k_out(const int* __restrict__ off, const int* __restrict__ odst,
                      const __half* __restrict__ hWh, const float* __restrict__ bo,
                      float* __restrict__ out) {
    const int w    = (blockIdx.x * 256 + threadIdx.x) >> 5;
    const int lane = threadIdx.x & 31;
    if (w >= N_NODES) return;

    float4 acc = *reinterpret_cast<const float4*>(bo + lane * 4);
    const int beg = off[w], end = off[w + 1];
#pragma unroll 4
    for (int i = beg; i < end; i++) {
        int d = odst[i];
        float4 v = ldh4(hWh + (size_t)d * 128 + lane * 4);
        acc.x += v.x; acc.y += v.y; acc.z += v.z; acc.w += v.w;
    }
    *reinterpret_cast<float4*>(out + (size_t)w * 128 + lane * 4) = acc;
}

// ---------------- launch ----------------------------------------------------
extern "C" void kernel_launch(void* const* d_in, const int* in_sizes, int n_in,
                              void* d_out, int out_size) {
    const float* x  = (const float*)d_in[0];
    const int*   ei = (const int*)d_in[1];     // int32 (JAX x64 disabled)
    const float* ea = (const float*)d_in[2];
    const float* We = (const float*)d_in[3];
    const float* be = (const float*)d_in[4];
    const float* Wg = (const float*)d_in[5];
    const float* bg = (const float*)d_in[6];
    // d_in[7]=Wa, d_in[8]=ba: dead (softmax over size-1 axis == 1)
    const float* Wo = (const float*)d_in[9];
    const float* bo = (const float*)d_in[10];
    float*       out = (float*)d_out;

    void *p;
    __half *xsh, *aggh, *hWh, *eawh, *Weh, *Wch;
    float *xd, *bgwo;
    int *din, *dout_, *oin, *oout, *cin, *cout_, *pos2, *odst;
    cudaGetSymbolAddress(&p, g_xd);          xd    = (float*)p;
    cudaGetSymbolAddress(&p, g_xsh);         xsh   = (__half*)p;
    cudaGetSymbolAddress(&p, g_aggh);        aggh  = (__half*)p;
    cudaGetSymbolAddress(&p, g_hWh);         hWh   = (__half*)p;
    cudaGetSymbolAddress(&p, g_eawh);        eawh  = (__half*)p;
    cudaGetSymbolAddress(&p, g_Weh);         Weh   = (__half*)p;
    cudaGetSymbolAddress(&p, g_Wch);         Wch   = (__half*)p;
    cudaGetSymbolAddress(&p, g_bgwo);        bgwo  = (float*)p;
    cudaGetSymbolAddress(&p, g_deg_in);      din   = (int*)p;
    cudaGetSymbolAddress(&p, g_deg_out);     dout_ = (int*)p;
    cudaGetSymbolAddress(&p, g_off_in);      oin   = (int*)p;
    cudaGetSymbolAddress(&p, g_off_out);     oout  = (int*)p;
    cudaGetSymbolAddress(&p, g_cur_in);      cin   = (int*)p;
    cudaGetSymbolAddress(&p, g_cur_out);     cout_ = (int*)p;
    cudaGetSymbolAddress(&p, g_pos2);        pos2  = (int*)p;
    cudaGetSymbolAddress(&p, g_csr_out_dst); odst  = (int*)p;

    const size_t mm_shmem  = 69632;           // sA + sB
    const size_t eaw_shmem = 70656;           // sA + sB + sSrc + sPos
    cudaFuncSetAttribute(k_mm<true,  false>, cudaFuncAttributeMaxDynamicSharedMemorySize, (int)mm_shmem);
    cudaFuncSetAttribute(k_mm<true,  true >, cudaFuncAttributeMaxDynamicSharedMemorySize, (int)mm_shmem);
    cudaFuncSetAttribute(k_mm<false, true >, cudaFuncAttributeMaxDynamicSharedMemorySize, (int)mm_shmem);
    cudaFuncSetAttribute(k_eaw,              cudaFuncAttributeMaxDynamicSharedMemorySize, (int)eaw_shmem);

    const int gblocks = NPAD / 128;           // 391
    const int eblocks = N_EDGES / 128;        // 6250
    const int nwarp_blocks = (N_NODES * 32 + 255) / 256;   // 6250

    k_f2h<<<(3 * WSZ + 255) / 256, 256>>>(We, Weh, 3 * WSZ);                        // 1
    k_zerodeg<<<(N_NODES + 255) / 256, 256>>>(din, dout_);                          // 2
    k_hist<<<(N_EDGES + 255) / 256, 256>>>(ei, din, dout_);                         // 3
    k_mm<true, true ><<<gblocks, 256, mm_shmem>>>(x, Weh + WSZ, nullptr, xsh, N_NODES); // 4 (profiled)
    k_scan2<<<2, 1024>>>(din, oin, cin, dout_, oout, cout_);                        // 5
    k_scatteridx<<<(N_EDGES + 255) / 256, 256>>>(ei, cin, cout_, pos2, odst);       // 6

    // edge GEMM + xs fold, scatter-written into in-CSR order
    k_eaw<<<eblocks, 256, eaw_shmem>>>(ea, ei, xsh, pos2, Weh + 2 * WSZ, eawh);     // 7

    k_wc<<<64, 256>>>(Wg, Wo, Wch);                                                 // 8
    k_bgwo<<<1, 128>>>(bg, Wo, bgwo);                                               // 9
    k_mm<true, false><<<gblocks, 256, mm_shmem>>>(x, Weh, be, xd, N_NODES);         // 10 (be folded)

    // fully sequential aggregation
    k_agg<<<nwarp_blocks, 256>>>(oin, xd, eawh, aggh);                              // 11

    // hW = agg @ (Wg@Wo) + bg@Wo
    k_mm<false, true><<<gblocks, 256, mm_shmem>>>(aggh, Wch, bgwo, hWh, NPAD);      // 12

    // out[n] = bo + sum hW[dst] over out-edges
    k_out<<<nwarp_blocks, 256>>>(oout, odst, hWh, bo, out);                         // 13
}

// round 11
// speedup vs baseline: 1.9135x; 1.0090x over previous
#include <cuda_runtime.h>
#include <cuda_fp16.h>
#include <mma.h>

using namespace nvcuda;

#define N_NODES 50000
#define N_EDGES 800000
#define HDIM    128
#define NPAD    50048           // ceil(N/128)*128
#define WSZ     (HDIM * HDIM)

// ---------------- scratch (device globals; no allocation allowed) ----------
__device__ float  g_xd   [NPAD * HDIM];              // x @ We0 + be (fp32)
__device__ __half g_xsh  [NPAD * HDIM];              // half(x @ We1)
__device__ __half g_aggh [NPAD * HDIM];              // half(segment_sum)
__device__ __half g_hWh  [NPAD * HDIM];              // half(agg @ Wc + bgwo)
__device__ __half g_eawh [(size_t)N_EDGES * HDIM];   // half(ea@We2 + xs[src]), CSR order
__device__ __half g_Weh  [3 * WSZ];
__device__ __half g_Wch  [WSZ];                      // half(Wg@Wo)
__device__ float  g_bgwo [HDIM];                     // bg@Wo
// CSR machinery
__device__ int  g_deg_in [N_NODES];
__device__ int  g_deg_out[N_NODES];
__device__ int  g_off_in [N_NODES + 1];
__device__ int  g_off_out[N_NODES + 1];
__device__ int  g_cur_in [N_NODES];
__device__ int  g_cur_out[N_NODES];
__device__ int  g_pos2   [N_EDGES];     // edge id -> in-CSR position
__device__ int  g_csr_out_dst[N_EDGES]; // out-CSR: dest node per out-edge

// ---------------- small utility kernels ------------------------------------
__global__ void k_hist(const int* __restrict__ ei, int* __restrict__ din, int* __restrict__ dout) {
    int e = blockIdx.x * 256 + threadIdx.x;
    if (e >= N_EDGES) return;
    atomicAdd(&dout[ei[e]], 1);            // src
    atomicAdd(&din[ei[N_EDGES + e]], 1);   // dst
}

// 2-block kernel: block 0 scans in-degrees, block 1 scans out-degrees
__global__ void k_scan2(const int* __restrict__ din, int* __restrict__ oin, int* __restrict__ cin,
                        const int* __restrict__ dout, int* __restrict__ oout, int* __restrict__ cout_) {
    const int* deg = blockIdx.x ? dout : din;
    int* off = blockIdx.x ? oout : oin;
    int* cur = blockIdx.x ? cout_ : cin;

    __shared__ int sp[1024];
    const int t = threadIdx.x;
    const int CH = 49;                               // 1024*49 >= 50000
    int start = t * CH;
    int end   = start + CH; if (end > N_NODES) end = N_NODES;
    int sum = 0;
    for (int i = start; i < end; i++) sum += deg[i];
    sp[t] = sum;
    __syncthreads();
    for (int d = 1; d < 1024; d <<= 1) {
        int v = (t >= d) ? sp[t - d] : 0;
        __syncthreads();
        sp[t] += v;
        __syncthreads();
    }
    int run = (t == 0) ? 0 : sp[t - 1];
    for (int i = start; i < end; i++) { off[i] = run; cur[i] = run; run += deg[i]; }
    if (start < N_NODES && end == N_NODES) off[N_NODES] = run;
}

__global__ void k_scatteridx(const int* __restrict__ ei,
                             int* __restrict__ cin, int* __restrict__ cout_,
                             int* __restrict__ pos2, int* __restrict__ odst) {
    int e = blockIdx.x * 256 + threadIdx.x;
    if (e >= N_EDGES) return;
    int s = ei[e];
    int d = ei[N_EDGES + e];
    int p1 = atomicAdd(&cin[d], 1);
    pos2[e] = p1;                          // eid -> csr position (sequential write)
    int p2 = atomicAdd(&cout_[s], 1);
    odst[p2] = d;
}

__global__ void k_f2h(const float* __restrict__ s, __half* __restrict__ d, int n) {
    int i = blockIdx.x * blockDim.x + threadIdx.x;
    if (i < n) d[i] = __float2half(s[i]);
}

// Wc = Wg @ Wo  (fp32 accumulate, round once to half)
__global__ void k_wc(const float* __restrict__ Wg, const float* __restrict__ Wo,
                     __half* __restrict__ Wch) {
    int i = blockIdx.x * blockDim.x + threadIdx.x;
    int r = i >> 7, c = i & 127;
    float s = 0.f;
#pragma unroll 8
    for (int k = 0; k < 128; k++) s += Wg[r * 128 + k] * Wo[k * 128 + c];
    Wch[i] = __float2half(s);
}

__global__ void k_bgwo(const float* __restrict__ bg, const float* __restrict__ Wo,
                       float* __restrict__ bgwo) {
    int c = threadIdx.x;
    float s = 0.f;
#pragma unroll 8
    for (int k = 0; k < 128; k++) s += bg[k] * Wo[k * 128 + c];
    bgwo[c] = s;
}

__device__ __forceinline__ float4 ldh4(const __half* p) {   // 4 halves via one 8B LDG
    uint2 u = *reinterpret_cast<const uint2*>(p);
    __half2 h0 = *reinterpret_cast<__half2*>(&u.x);
    __half2 h1 = *reinterpret_cast<__half2*>(&u.y);
    float2 f0 = __half22float2(h0);
    float2 f1 = __half22float2(h1);
    return make_float4(f0.x, f0.y, f1.x, f1.y);
}

// ---------------- unified [M,128]@[128,128] GEMM ----------------------------
template <bool A_FP32, bool HALF_OUT>
__global__ void k_mm(const void* __restrict__ Av, const __half* __restrict__ B,
                     const float* __restrict__ bias, void* __restrict__ C, int m_rows) {
    extern __shared__ char smem[];
    __half* sA = reinterpret_cast<__half*>(smem);            // 128 x 136 halves
    __half* sB = reinterpret_cast<__half*>(smem + 34816);    // 128 x 136 halves
    float*  sT = reinterpret_cast<float*>(smem);             // reused staging

    const int tid  = threadIdx.x;
    const int warp = tid >> 5;
    const int lane = tid & 31;
    const size_t r0 = (size_t)blockIdx.x * 128;

    if (A_FP32) {
        const float* A = (const float*)Av;
#pragma unroll
        for (int j = 0; j < 16; j++) {
            int idx = j * 256 + tid;
            int row = idx >> 5, c4 = idx & 31;
            float4 v = make_float4(0.f, 0.f, 0.f, 0.f);
            if ((int)(r0 + row) < m_rows)
                v = *reinterpret_cast<const float4*>(A + (r0 + row) * 128 + c4 * 4);
            *reinterpret_cast<__half2*>(sA + row * 136 + c4 * 4)     = __floats2half2_rn(v.x, v.y);
            *reinterpret_cast<__half2*>(sA + row * 136 + c4 * 4 + 2) = __floats2half2_rn(v.z, v.w);
        }
    } else {
        const __half* A = (const __half*)Av;
#pragma unroll
        for (int j = 0; j < 32; j++) {
            int idx = j * 256 + tid;
            int row = idx >> 6, c2 = idx & 63;
            __half2 v = __floats2half2_rn(0.f, 0.f);
            if ((int)(r0 + row) < m_rows)
                v = *reinterpret_cast<const __half2*>(A + (r0 + row) * 128 + c2 * 2);
            *reinterpret_cast<__half2*>(sA + row * 136 + c2 * 2) = v;
        }
    }
#pragma unroll
    for (int j = 0; j < 32; j++) {                   // stage B
        int idx = j * 256 + tid;
        int row = idx >> 6, c2 = idx & 63;
        *reinterpret_cast<__half2*>(sB + row * 136 + c2 * 2) =
            *reinterpret_cast<const __half2*>(B + row * 128 + c2 * 2);
    }
    __syncthreads();

    wmma::fragment<wmma::accumulator, 16, 16, 16, float> acc[8];
#pragma unroll
    for (int n = 0; n < 8; n++) wmma::fill_fragment(acc[n], 0.f);

#pragma unroll
    for (int k = 0; k < 8; k++) {
        wmma::fragment<wmma::matrix_a, 16, 16, 16, __half, wmma::row_major> a;
        wmma::load_matrix_sync(a, sA + warp * 16 * 136 + k * 16, 136);
#pragma unroll
        for (int n = 0; n < 8; n++) {
            wmma::fragment<wmma::matrix_b, 16, 16, 16, __half, wmma::row_major> b;
            wmma::load_matrix_sync(b, sB + (k * 16) * 136 + n * 16, 136);
            wmma::mma_sync(acc[n], a, b, acc[n]);
        }
    }
    __syncthreads();                                 // done with sA/sB

    float* my = sT + warp * 16 * 132;
#pragma unroll
    for (int n = 0; n < 8; n++)
        wmma::store_matrix_sync(my + n * 16, acc[n], 132, wmma::mem_row_major);
    __syncwarp();                                    // each warp reads its own rows

    float4 bv = make_float4(0.f, 0.f, 0.f, 0.f);
    if (bias) bv = *reinterpret_cast<const float4*>(bias + lane * 4);

    const size_t row0 = r0 + warp * 16;
#pragma unroll
    for (int r = 0; r < 16; r++) {
        float4 v = *reinterpret_cast<const float4*>(my + r * 132 + lane * 4);
        v.x += bv.x; v.y += bv.y; v.z += bv.z; v.w += bv.w;
        if (HALF_OUT) {
            __half2 h0 = __floats2half2_rn(v.x, v.y);
            __half2 h1 = __floats2half2_rn(v.z, v.w);
            uint2 u = make_uint2(*(unsigned*)&h0, *(unsigned*)&h1);
            *reinterpret_cast<uint2*>((__half*)C + (row0 + r) * 128 + lane * 4) = u;
        } else {
            *reinterpret_cast<float4*>((float*)C + (row0 + r) * 128 + lane * 4) = v;
        }
    }
}

// ------- edge GEMM + xs fold + CSR scatter-write ----------------------------
// eawh[pos2[e]] = half( ea[e]@We2 + xs[src[e]] )
// xs gathers are register-prefetched BEFORE the mma so their L2 latency hides
// under the tensor op; epilogue is warp-local (one sync fewer, warps retire
// independently).
__global__ void k_eaw(const float* __restrict__ ea, const int* __restrict__ ei,
                      const __half* __restrict__ xsh, const int* __restrict__ pos2,
                      const __half* __restrict__ W2, __half* __restrict__ eaw) {
    extern __shared__ char smem[];
    __half* sA   = reinterpret_cast<__half*>(smem);            // 128 x 136
    __half* sB   = reinterpret_cast<__half*>(smem + 34816);    // 128 x 136
    int*    sSrc = reinterpret_cast<int*>(smem + 69632);       // 128
    int*    sPos = reinterpret_cast<int*>(smem + 70144);       // 128
    float*  sT   = reinterpret_cast<float*>(smem);             // per-warp strips, reuse sA/sB

    const int tid  = threadIdx.x;
    const int warp = tid >> 5;
    const int lane = tid & 31;
    const size_t e0 = (size_t)blockIdx.x * 128;

    if (tid < 128) {
        sSrc[tid] = ei[e0 + tid];                    // src = edge_index[0]
        sPos[tid] = pos2[e0 + tid];
    }
#pragma unroll
    for (int j = 0; j < 16; j++) {                   // stream A tile (sequential DRAM)
        int idx = j * 256 + tid;
        int row = idx >> 5, c4 = idx & 31;
        float4 v = *reinterpret_cast<const float4*>(ea + (e0 + row) * 128 + c4 * 4);
        *reinterpret_cast<__half2*>(sA + row * 136 + c4 * 4)     = __floats2half2_rn(v.x, v.y);
        *reinterpret_cast<__half2*>(sA + row * 136 + c4 * 4 + 2) = __floats2half2_rn(v.z, v.w);
    }
#pragma unroll
    for (int j = 0; j < 32; j++) {                   // stage W2 (L2-resident)
        int idx = j * 256 + tid;
        int row = idx >> 6, c2 = idx & 63;
        *reinterpret_cast<__half2*>(sB + row * 136 + c2 * 2) =
            *reinterpret_cast<const __half2*>(W2 + row * 128 + c2 * 2);
    }
    __syncthreads();

    // prefetch xs[src] for this warp's 16 rows — independent of the mma,
    // issued now so the L2 latency overlaps the tensor work below.
    uint2 pre[16];
#pragma unroll
    for (int r = 0; r < 16; r++) {
        int src = sSrc[warp * 16 + r];
        pre[r] = *reinterpret_cast<const uint2*>(xsh + (size_t)src * 128 + lane * 4);
    }

    wmma::fragment<wmma::accumulator, 16, 16, 16, float> acc[8];
#pragma unroll
    for (int n = 0; n < 8; n++) wmma::fill_fragment(acc[n], 0.f);

#pragma unroll
    for (int k = 0; k < 8; k++) {
        wmma::fragment<wmma::matrix_a, 16, 16, 16, __half, wmma::row_major> a;
        wmma::load_matrix_sync(a, sA + warp * 16 * 136 + k * 16, 136);
#pragma unroll
        for (int n = 0; n < 8; n++) {
            wmma::fragment<wmma::matrix_b, 16, 16, 16, __half, wmma::row_major> b;
            wmma::load_matrix_sync(b, sB + (k * 16) * 136 + n * 16, 136);
            wmma::mma_sync(acc[n], a, b, acc[n]);
        }
    }
    __syncthreads();                                 // all warps done reading sA/sB

    // warp-local epilogue: private 16x132 fp32 strip (overlaps sA/sB region)
    float* my = sT + warp * (16 * 132);
#pragma unroll
    for (int n = 0; n < 8; n++)
        wmma::store_matrix_sync(my + n * 16, acc[n], 132, wmma::mem_row_major);
    __syncwarp();

#pragma unroll
    for (int r = 0; r < 16; r++) {
        int row = warp * 16 + r;
        float4 t = *reinterpret_cast<const float4*>(my + r * 132 + lane * 4);
        __half2 p0 = *reinterpret_cast<__half2*>(&pre[r].x);
        __half2 p1 = *reinterpret_cast<__half2*>(&pre[r].y);
        float2 v0 = __half22float2(p0);
        float2 v1 = __half22float2(p1);
        __half2 h0 = __floats2half2_rn(t.x + v0.x, t.y + v0.y);
        __half2 h1 = __floats2half2_rn(t.z + v1.x, t.w + v1.y);
        uint2 u = make_uint2(*(unsigned*)&h0, *(unsigned*)&h1);
        *reinterpret_cast<uint2*>(eaw + (size_t)sPos[row] * 128 + lane * 4) = u;
    }
}

// ------- aggregation: aggh[n] = half( sum silu(xd[n] + eawh[i]) ), sequential
__device__ __forceinline__ float silu1(float v) { return v / (1.f + __expf(-v)); }

__global__ void k_agg(const int* __restrict__ off,
                      const float* __restrict__ xd, const __half* __restrict__ eaw,
                      __half* __restrict__ aggh) {
    const int w    = (blockIdx.x * 256 + threadIdx.x) >> 5;    // node id
    const int lane = threadIdx.x & 31;
    if (w >= N_NODES) return;

    float4 base = *reinterpret_cast<const float4*>(xd + (size_t)w * 128 + lane * 4);

    float4 acc = make_float4(0.f, 0.f, 0.f, 0.f);
    const int beg = off[w], end = off[w + 1];
#pragma unroll 4
    for (int i = beg; i < end; i++) {                // sequential eaw stream
        float4 t = ldh4(eaw + (size_t)i * 128 + lane * 4);
        acc.x += silu1(base.x + t.x);
        acc.y += silu1(base.y + t.y);
        acc.z += silu1(base.z + t.z);
        acc.w += silu1(base.w + t.w);
    }
    __half2 h0 = __floats2half2_rn(acc.x, acc.y);
    __half2 h1 = __floats2half2_rn(acc.z, acc.w);
    uint2 u = make_uint2(*(unsigned*)&h0, *(unsigned*)&h1);
    *reinterpret_cast<uint2*>(aggh + (size_t)w * 128 + lane * 4) = u;
}

// ---------------- output: out[n] = bo + sum_out hW[dst] ---------------------
__global__ void k_out(const int* __restrict__ off, const int* __restrict__ odst,
                      const __half* __restrict__ hWh, const float* __restrict__ bo,
                      float* __restrict__ out) {
    const int w    = (blockIdx.x * 256 + threadIdx.x) >> 5;
    const int lane = threadIdx.x & 31;
    if (w >= N_NODES) return;

    float4 acc = *reinterpret_cast<const float4*>(bo + lane * 4);
    const int beg = off[w], end = off[w + 1];
#pragma unroll 4
    for (int i = beg; i < end; i++) {
        int d = odst[i];
        float4 v = ldh4(hWh + (size_t)d * 128 + lane * 4);
        acc.x += v.x; acc.y += v.y; acc.z += v.z; acc.w += v.w;
    }
    *reinterpret_cast<float4*>(out + (size_t)w * 128 + lane * 4) = acc;
}

// ---------------- launch ----------------------------------------------------
extern "C" void kernel_launch(void* const* d_in, const int* in_sizes, int n_in,
                              void* d_out, int out_size) {
    const float* x  = (const float*)d_in[0];
    const int*   ei = (const int*)d_in[1];     // int32 (JAX x64 disabled)
    const float* ea = (const float*)d_in[2];
    const float* We = (const float*)d_in[3];
    const float* be = (const float*)d_in[4];
    const float* Wg = (const float*)d_in[5];
    const float* bg = (const float*)d_in[6];
    // d_in[7]=Wa, d_in[8]=ba: dead (softmax over size-1 axis == 1)
    const float* Wo = (const float*)d_in[9];
    const float* bo = (const float*)d_in[10];
    float*       out = (float*)d_out;

    void *p;
    __half *xsh, *aggh, *hWh, *eawh, *Weh, *Wch;
    float *xd, *bgwo;
    int *din, *dout_, *oin, *oout, *cin, *cout_, *pos2, *odst;
    cudaGetSymbolAddress(&p, g_xd);          xd    = (float*)p;
    cudaGetSymbolAddress(&p, g_xsh);         xsh   = (__half*)p;
    cudaGetSymbolAddress(&p, g_aggh);        aggh  = (__half*)p;
    cudaGetSymbolAddress(&p, g_hWh);         hWh   = (__half*)p;
    cudaGetSymbolAddress(&p, g_eawh);        eawh  = (__half*)p;
    cudaGetSymbolAddress(&p, g_Weh);         Weh   = (__half*)p;
    cudaGetSymbolAddress(&p, g_Wch);         Wch   = (__half*)p;
    cudaGetSymbolAddress(&p, g_bgwo);        bgwo  = (float*)p;
    cudaGetSymbolAddress(&p, g_deg_in);      din   = (int*)p;
    cudaGetSymbolAddress(&p, g_deg_out);     dout_ = (int*)p;
    cudaGetSymbolAddress(&p, g_off_in);      oin   = (int*)p;
    cudaGetSymbolAddress(&p, g_off_out);     oout  = (int*)p;
    cudaGetSymbolAddress(&p, g_cur_in);      cin   = (int*)p;
    cudaGetSymbolAddress(&p, g_cur_out);     cout_ = (int*)p;
    cudaGetSymbolAddress(&p, g_pos2);        pos2  = (int*)p;
    cudaGetSymbolAddress(&p, g_csr_out_dst); odst  = (int*)p;

    const size_t mm_shmem  = 69632;           // sA + sB
    const size_t eaw_shmem = 70656;           // sA + sB + sSrc + sPos
    cudaFuncSetAttribute(k_mm<true,  false>, cudaFuncAttributeMaxDynamicSharedMemorySize, (int)mm_shmem);
    cudaFuncSetAttribute(k_mm<true,  true >, cudaFuncAttributeMaxDynamicSharedMemorySize, (int)mm_shmem);
    cudaFuncSetAttribute(k_mm<false, true >, cudaFuncAttributeMaxDynamicSharedMemorySize, (int)mm_shmem);
    cudaFuncSetAttribute(k_eaw,              cudaFuncAttributeMaxDynamicSharedMemorySize, (int)eaw_shmem);

    const int gblocks = NPAD / 128;           // 391
    const int eblocks = N_EDGES / 128;        // 6250
    const int nwarp_blocks = (N_NODES * 32 + 255) / 256;   // 6250

    cudaMemsetAsync(din,   0, N_NODES * sizeof(int));
    cudaMemsetAsync(dout_, 0, N_NODES * sizeof(int));

    k_f2h<<<(3 * WSZ + 255) / 256, 256>>>(We, Weh, 3 * WSZ);                        // 1
    k_hist<<<(N_EDGES + 255) / 256, 256>>>(ei, din, dout_);                         // 2
    k_mm<true, true ><<<gblocks, 256, mm_shmem>>>(x, Weh + WSZ, nullptr, xsh, N_NODES); // 3
    k_scan2<<<2, 1024>>>(din, oin, cin, dout_, oout, cout_);                        // 4
    k_scatteridx<<<(N_EDGES + 255) / 256, 256>>>(ei, cin, cout_, pos2, odst);       // 5

    // edge GEMM + xs fold, scatter-written into in-CSR order
    k_eaw<<<eblocks, 256, eaw_shmem>>>(ea, ei, xsh, pos2, Weh + 2 * WSZ, eawh);     // 6

    k_wc<<<64, 256>>>(Wg, Wo, Wch);                                                 // 7
    k_bgwo<<<1, 128>>>(bg, Wo, bgwo);                                               // 8
    k_mm<true, false><<<gblocks, 256, mm_shmem>>>(x, Weh, be, xd, N_NODES);         // 9 (be folded)

    // fully sequential aggregation
    k_agg<<<nwarp_blocks, 256>>>(oin, xd, eawh, aggh);                              // 10

    // hW = agg @ (Wg@Wo) + bg@Wo
    k_mm<false, true><<<gblocks, 256, mm_shmem>>>(aggh, Wch, bgwo, hWh, NPAD);      // 11

    // out[n] = bo + sum hW[dst] over out-edges
    k_out<<<nwarp_blocks, 256>>>(oout, odst, hWh, bo, out);                         // 12
}

// round 12
// speedup vs baseline: 2.2482x; 1.1750x over previous
#include <cuda_runtime.h>
#include <cuda_fp16.h>
#include <mma.h>

using namespace nvcuda;

#define N_NODES 50000
#define N_EDGES 800000
#define HDIM    128
#define NPAD    50048           // ceil(N/128)*128
#define WSZ     (HDIM * HDIM)
#define SCAN_BLOCKS 98          // 98 * 512 = 50176 >= N_NODES

// ---------------- scratch (device globals; no allocation allowed) ----------
__device__ float  g_xd   [NPAD * HDIM];              // x @ We0 + be (fp32)
__device__ __half g_xsh  [NPAD * HDIM];              // half(x @ We1)
__device__ __half g_aggh [NPAD * HDIM];              // half(segment_sum)
__device__ __half g_hWh  [NPAD * HDIM];              // half(agg @ Wc + bgwo)
__device__ __half g_eawh [(size_t)N_EDGES * HDIM];   // half(ea@We2 + xs[src]), CSR order
__device__ __half g_Weh  [3 * WSZ];
__device__ __half g_Wch  [WSZ];                      // half(Wg@Wo)
__device__ float  g_bgwo [HDIM];                     // bg@Wo
// CSR machinery
__device__ int  g_deg_in [N_NODES];
__device__ int  g_deg_out[N_NODES];
__device__ int  g_off_in [N_NODES + 1];
__device__ int  g_off_out[N_NODES + 1];
__device__ int  g_cur_in [N_NODES];
__device__ int  g_cur_out[N_NODES];
__device__ int  g_bsum   [2 * SCAN_BLOCKS];
__device__ int  g_pos2   [N_EDGES];     // edge id -> in-CSR position
__device__ int  g_csr_out_dst[N_EDGES]; // out-CSR: dest node per out-edge

// ---------------- small utility kernels ------------------------------------
__global__ void k_hist(const int* __restrict__ ei, int* __restrict__ din, int* __restrict__ dout) {
    int e = blockIdx.x * 256 + threadIdx.x;
    if (e >= N_EDGES) return;
    atomicAdd(&dout[ei[e]], 1);            // src
    atomicAdd(&din[ei[N_EDGES + e]], 1);   // dst
}

// Phase A: per-block (512-elem) degree sums. grid = 2*SCAN_BLOCKS.
__global__ void k_blocksum(const int* __restrict__ din, const int* __restrict__ dout,
                           int* __restrict__ bsum) {
    const int* deg = (blockIdx.x < SCAN_BLOCKS) ? din : dout;
    const int b = (blockIdx.x < SCAN_BLOCKS) ? blockIdx.x : blockIdx.x - SCAN_BLOCKS;
    const int i = b * 512 + threadIdx.x;
    int v = (i < N_NODES) ? deg[i] : 0;

    __shared__ int ws[16];
    const int lane = threadIdx.x & 31, w = threadIdx.x >> 5;
#pragma unroll
    for (int o = 16; o; o >>= 1) v += __shfl_down_sync(0xffffffffu, v, o);
    if (lane == 0) ws[w] = v;
    __syncthreads();
    if (threadIdx.x < 16) {
        int t = ws[threadIdx.x];
#pragma unroll
        for (int o = 8; o; o >>= 1) t += __shfl_down_sync(0xffffu, t, o);
        if (threadIdx.x == 0) bsum[blockIdx.x] = t;
    }
}

// Phase B: exclusive scan of each 98-entry segment. grid = 2, block = 128.
__global__ void k_bscan(int* __restrict__ bsum, int* __restrict__ oin, int* __restrict__ oout) {
    __shared__ int sp[128];
    const int base = blockIdx.x * SCAN_BLOCKS;
    const int t = threadIdx.x;
    int v = (t < SCAN_BLOCKS) ? bsum[base + t] : 0;
    sp[t] = v;
    __syncthreads();
#pragma unroll
    for (int d = 1; d < 128; d <<= 1) {
        int u = (t >= d) ? sp[t - d] : 0;
        __syncthreads();
        sp[t] += u;
        __syncthreads();
    }
    if (t < SCAN_BLOCKS) bsum[base + t] = sp[t] - v;   // exclusive
    if (t == 0) (blockIdx.x ? oout : oin)[N_NODES] = N_EDGES;
}

// Phase C: per-block exclusive scan + block offset -> off/cur. grid = 2*SCAN_BLOCKS.
__global__ void k_scatteroff(const int* __restrict__ din, const int* __restrict__ dout,
                             const int* __restrict__ bsum,
                             int* __restrict__ oin, int* __restrict__ cin,
                             int* __restrict__ oout, int* __restrict__ cout_) {
    const bool isout = blockIdx.x >= SCAN_BLOCKS;
    const int* deg = isout ? dout : din;
    int* off = isout ? oout : oin;
    int* cur = isout ? cout_ : cin;
    const int b = isout ? blockIdx.x - SCAN_BLOCKS : blockIdx.x;
    const int i = b * 512 + threadIdx.x;
    int v = (i < N_NODES) ? deg[i] : 0;

    const int lane = threadIdx.x & 31, w = threadIdx.x >> 5;
    int incl = v;
#pragma unroll
    for (int o = 1; o < 32; o <<= 1) {
        int u = __shfl_up_sync(0xffffffffu, incl, o);
        if (lane >= o) incl += u;
    }
    __shared__ int ws[16], wo[16];
    if (lane == 31) ws[w] = incl;
    __syncthreads();
    if (threadIdx.x < 16) {
        int t = ws[threadIdx.x];
        int ti = t;
#pragma unroll
        for (int o = 1; o < 16; o <<= 1) {
            int u = __shfl_up_sync(0xffffu, ti, o);
            if (threadIdx.x >= o) ti += u;
        }
        wo[threadIdx.x] = ti - t;                      // exclusive warp offset
    }
    __syncthreads();
    int excl = incl - v + wo[w] + bsum[blockIdx.x];
    if (i < N_NODES) { off[i] = excl; cur[i] = excl; }
}

__global__ void k_scatteridx(const int* __restrict__ ei,
                             int* __restrict__ cin, int* __restrict__ cout_,
                             int* __restrict__ pos2, int* __restrict__ odst) {
    int e = blockIdx.x * 256 + threadIdx.x;
    if (e >= N_EDGES) return;
    int s = ei[e];
    int d = ei[N_EDGES + e];
    int p1 = atomicAdd(&cin[d], 1);
    pos2[e] = p1;                          // eid -> csr position (sequential write)
    int p2 = atomicAdd(&cout_[s], 1);
    odst[p2] = d;
}

__global__ void k_f2h(const float* __restrict__ s, __half* __restrict__ d, int n) {
    int i = blockIdx.x * blockDim.x + threadIdx.x;
    if (i < n) d[i] = __float2half(s[i]);
}

// Wc = Wg @ Wo  (fp32 accumulate, round once to half)
__global__ void k_wc(const float* __restrict__ Wg, const float* __restrict__ Wo,
                     __half* __restrict__ Wch) {
    int i = blockIdx.x * blockDim.x + threadIdx.x;
    int r = i >> 7, c = i & 127;
    float s = 0.f;
#pragma unroll 8
    for (int k = 0; k < 128; k++) s += Wg[r * 128 + k] * Wo[k * 128 + c];
    Wch[i] = __float2half(s);
}

__global__ void k_bgwo(const float* __restrict__ bg, const float* __restrict__ Wo,
                       float* __restrict__ bgwo) {
    int c = threadIdx.x;
    float s = 0.f;
#pragma unroll 8
    for (int k = 0; k < 128; k++) s += bg[k] * Wo[k * 128 + c];
    bgwo[c] = s;
}

__device__ __forceinline__ float4 ldh4(const __half* p) {   // 4 halves via one 8B LDG
    uint2 u = *reinterpret_cast<const uint2*>(p);
    __half2 h0 = *reinterpret_cast<__half2*>(&u.x);
    __half2 h1 = *reinterpret_cast<__half2*>(&u.y);
    float2 f0 = __half22float2(h0);
    float2 f1 = __half22float2(h1);
    return make_float4(f0.x, f0.y, f1.x, f1.y);
}

// ---------------- unified [M,128]@[128,128] GEMM ----------------------------
template <bool A_FP32, bool HALF_OUT>
__global__ void k_mm(const void* __restrict__ Av, const __half* __restrict__ B,
                     const float* __restrict__ bias, void* __restrict__ C, int m_rows) {
    extern __shared__ char smem[];
    __half* sA = reinterpret_cast<__half*>(smem);            // 128 x 136 halves
    __half* sB = reinterpret_cast<__half*>(smem + 34816);    // 128 x 136 halves
    float*  sT = reinterpret_cast<float*>(smem);             // reused staging

    const int tid  = threadIdx.x;
    const int warp = tid >> 5;
    const int lane = tid & 31;
    const size_t r0 = (size_t)blockIdx.x * 128;

    if (A_FP32) {
        const float* A = (const float*)Av;
#pragma unroll
        for (int j = 0; j < 16; j++) {
            int idx = j * 256 + tid;
            int row = idx >> 5, c4 = idx & 31;
            float4 v = make_float4(0.f, 0.f, 0.f, 0.f);
            if ((int)(r0 + row) < m_rows)
                v = *reinterpret_cast<const float4*>(A + (r0 + row) * 128 + c4 * 4);
            *reinterpret_cast<__half2*>(sA + row * 136 + c4 * 4)     = __floats2half2_rn(v.x, v.y);
            *reinterpret_cast<__half2*>(sA + row * 136 + c4 * 4 + 2) = __floats2half2_rn(v.z, v.w);
        }
    } else {
        const __half* A = (const __half*)Av;
#pragma unroll
        for (int j = 0; j < 32; j++) {
            int idx = j * 256 + tid;
            int row = idx >> 6, c2 = idx & 63;
            __half2 v = __floats2half2_rn(0.f, 0.f);
            if ((int)(r0 + row) < m_rows)
                v = *reinterpret_cast<const __half2*>(A + (r0 + row) * 128 + c2 * 2);
            *reinterpret_cast<__half2*>(sA + row * 136 + c2 * 2) = v;
        }
    }
#pragma unroll
    for (int j = 0; j < 32; j++) {                   // stage B
        int idx = j * 256 + tid;
        int row = idx >> 6, c2 = idx & 63;
        *reinterpret_cast<__half2*>(sB + row * 136 + c2 * 2) =
            *reinterpret_cast<const __half2*>(B + row * 128 + c2 * 2);
    }
    __syncthreads();

    wmma::fragment<wmma::accumulator, 16, 16, 16, float> acc[8];
#pragma unroll
    for (int n = 0; n < 8; n++) wmma::fill_fragment(acc[n], 0.f);

#pragma unroll
    for (int k = 0; k < 8; k++) {
        wmma::fragment<wmma::matrix_a, 16, 16, 16, __half, wmma::row_major> a;
        wmma::load_matrix_sync(a, sA + warp * 16 * 136 + k * 16, 136);
#pragma unroll
        for (int n = 0; n < 8; n++) {
            wmma::fragment<wmma::matrix_b, 16, 16, 16, __half, wmma::row_major> b;
            wmma::load_matrix_sync(b, sB + (k * 16) * 136 + n * 16, 136);
            wmma::mma_sync(acc[n], a, b, acc[n]);
        }
    }
    __syncthreads();                                 // done with sA/sB

    float* my = sT + warp * 16 * 132;
#pragma unroll
    for (int n = 0; n < 8; n++)
        wmma::store_matrix_sync(my + n * 16, acc[n], 132, wmma::mem_row_major);
    __syncwarp();                                    // each warp reads its own rows

    float4 bv = make_float4(0.f, 0.f, 0.f, 0.f);
    if (bias) bv = *reinterpret_cast<const float4*>(bias + lane * 4);

    const size_t row0 = r0 + warp * 16;
#pragma unroll
    for (int r = 0; r < 16; r++) {
        float4 v = *reinterpret_cast<const float4*>(my + r * 132 + lane * 4);
        v.x += bv.x; v.y += bv.y; v.z += bv.z; v.w += bv.w;
        if (HALF_OUT) {
            __half2 h0 = __floats2half2_rn(v.x, v.y);
            __half2 h1 = __floats2half2_rn(v.z, v.w);
            uint2 u = make_uint2(*(unsigned*)&h0, *(unsigned*)&h1);
            *reinterpret_cast<uint2*>((__half*)C + (row0 + r) * 128 + lane * 4) = u;
        } else {
            *reinterpret_cast<float4*>((float*)C + (row0 + r) * 128 + lane * 4) = v;
        }
    }
}

// ------- edge GEMM + xs fold + CSR scatter-write ----------------------------
__global__ void k_eaw(const float* __restrict__ ea, const int* __restrict__ ei,
                      const __half* __restrict__ xsh, const int* __restrict__ pos2,
                      const __half* __restrict__ W2, __half* __restrict__ eaw) {
    extern __shared__ char smem[];
    __half* sA   = reinterpret_cast<__half*>(smem);            // 128 x 136
    __half* sB   = reinterpret_cast<__half*>(smem + 34816);    // 128 x 136
    int*    sSrc = reinterpret_cast<int*>(smem + 69632);       // 128
    int*    sPos = reinterpret_cast<int*>(smem + 70144);       // 128
    float*  sT   = reinterpret_cast<float*>(smem);             // per-warp strips

    const int tid  = threadIdx.x;
    const int warp = tid >> 5;
    const int lane = tid & 31;
    const size_t e0 = (size_t)blockIdx.x * 128;

    if (tid < 128) {
        sSrc[tid] = ei[e0 + tid];                    // src = edge_index[0]
        sPos[tid] = pos2[e0 + tid];
    }
#pragma unroll
    for (int j = 0; j < 16; j++) {                   // stream A tile (sequential DRAM)
        int idx = j * 256 + tid;
        int row = idx >> 5, c4 = idx & 31;
        float4 v = *reinterpret_cast<const float4*>(ea + (e0 + row) * 128 + c4 * 4);
        *reinterpret_cast<__half2*>(sA + row * 136 + c4 * 4)     = __floats2half2_rn(v.x, v.y);
        *reinterpret_cast<__half2*>(sA + row * 136 + c4 * 4 + 2) = __floats2half2_rn(v.z, v.w);
    }
#pragma unroll
    for (int j = 0; j < 32; j++) {                   // stage W2 (L2-resident)
        int idx = j * 256 + tid;
        int row = idx >> 6, c2 = idx & 63;
        *reinterpret_cast<__half2*>(sB + row * 136 + c2 * 2) =
            *reinterpret_cast<const __half2*>(W2 + row * 128 + c2 * 2);
    }
    __syncthreads();

    // prefetch xs[src] for this warp's 16 rows — latency hides under the mma
    uint2 pre[16];
#pragma unroll
    for (int r = 0; r < 16; r++) {
        int src = sSrc[warp * 16 + r];
        pre[r] = *reinterpret_cast<const uint2*>(xsh + (size_t)src * 128 + lane * 4);
    }

    wmma::fragment<wmma::accumulator, 16, 16, 16, float> acc[8];
#pragma unroll
    for (int n = 0; n < 8; n++) wmma::fill_fragment(acc[n], 0.f);

#pragma unroll
    for (int k = 0; k < 8; k++) {
        wmma::fragment<wmma::matrix_a, 16, 16, 16, __half, wmma::row_major> a;
        wmma::load_matrix_sync(a, sA + warp * 16 * 136 + k * 16, 136);
#pragma unroll
        for (int n = 0; n < 8; n++) {
            wmma::fragment<wmma::matrix_b, 16, 16, 16, __half, wmma::row_major> b;
            wmma::load_matrix_sync(b, sB + (k * 16) * 136 + n * 16, 136);
            wmma::mma_sync(acc[n], a, b, acc[n]);
        }
    }
    __syncthreads();                                 // all warps done reading sA/sB

    // warp-local epilogue
    float* my = sT + warp * (16 * 132);
#pragma unroll
    for (int n = 0; n < 8; n++)
        wmma::store_matrix_sync(my + n * 16, acc[n], 132, wmma::mem_row_major);
    __syncwarp();

#pragma unroll
    for (int r = 0; r < 16; r++) {
        int row = warp * 16 + r;
        float4 t = *reinterpret_cast<const float4*>(my + r * 132 + lane * 4);
        __half2 p0 = *reinterpret_cast<__half2*>(&pre[r].x);
        __half2 p1 = *reinterpret_cast<__half2*>(&pre[r].y);
        float2 v0 = __half22float2(p0);
        float2 v1 = __half22float2(p1);
        __half2 h0 = __floats2half2_rn(t.x + v0.x, t.y + v0.y);
        __half2 h1 = __floats2half2_rn(t.z + v1.x, t.w + v1.y);
        uint2 u = make_uint2(*(unsigned*)&h0, *(unsigned*)&h1);
        *reinterpret_cast<uint2*>(eaw + (size_t)sPos[row] * 128 + lane * 4) = u;
    }
}

// ------- aggregation: aggh[n] = half( sum silu(xd[n] + eawh[i]) ), sequential
__device__ __forceinline__ float silu1(float v) { return v / (1.f + __expf(-v)); }

__global__ void k_agg(const int* __restrict__ off,
                      const float* __restrict__ xd, const __half* __restrict__ eaw,
                      __half* __restrict__ aggh) {
    const int w    = (blockIdx.x * 256 + threadIdx.x) >> 5;    // node id
    const int lane = threadIdx.x & 31;
    if (w >= N_NODES) return;

    float4 base = *reinterpret_cast<const float4*>(xd + (size_t)w * 128 + lane * 4);

    float4 acc = make_float4(0.f, 0.f, 0.f, 0.f);
    const int beg = off[w], end = off[w + 1];
#pragma unroll 4
    for (int i = beg; i < end; i++) {                // sequential eaw stream
        float4 t = ldh4(eaw + (size_t)i * 128 + lane * 4);
        acc.x += silu1(base.x + t.x);
        acc.y += silu1(base.y + t.y);
        acc.z += silu1(base.z + t.z);
        acc.w += silu1(base.w + t.w);
    }
    __half2 h0 = __floats2half2_rn(acc.x, acc.y);
    __half2 h1 = __floats2half2_rn(acc.z, acc.w);
    uint2 u = make_uint2(*(unsigned*)&h0, *(unsigned*)&h1);
    *reinterpret_cast<uint2*>(aggh + (size_t)w * 128 + lane * 4) = u;
}

// ---------------- output: out[n] = bo + sum_out hW[dst] ---------------------
__global__ void k_out(const int* __restrict__ off, const int* __restrict__ odst,
                      const __half* __restrict__ hWh, const float* __restrict__ bo,
                      float* __restrict__ out) {
    const int w    = (blockIdx.x * 256 + threadIdx.x) >> 5;
    const int lane = threadIdx.x & 31;
    if (w >= N_NODES) return;

    float4 acc = *reinterpret_cast<const float4*>(bo + lane * 4);
    const int beg = off[w], end = off[w + 1];
#pragma unroll 4
    for (int i = beg; i < end; i++) {
        int d = odst[i];
        float4 v = ldh4(hWh + (size_t)d * 128 + lane * 4);
        acc.x += v.x; acc.y += v.y; acc.z += v.z; acc.w += v.w;
    }
    *reinterpret_cast<float4*>(out + (size_t)w * 128 + lane * 4) = acc;
}

// ---------------- launch ----------------------------------------------------
extern "C" void kernel_launch(void* const* d_in, const int* in_sizes, int n_in,
                              void* d_out, int out_size) {
    const float* x  = (const float*)d_in[0];
    const int*   ei = (const int*)d_in[1];     // int32 (JAX x64 disabled)
    const float* ea = (const float*)d_in[2];
    const float* We = (const float*)d_in[3];
    const float* be = (const float*)d_in[4];
    const float* Wg = (const float*)d_in[5];
    const float* bg = (const float*)d_in[6];
    // d_in[7]=Wa, d_in[8]=ba: dead (softmax over size-1 axis == 1)
    const float* Wo = (const float*)d_in[9];
    const float* bo = (const float*)d_in[10];
    float*       out = (float*)d_out;

    void *p;
    __half *xsh, *aggh, *hWh, *eawh, *Weh, *Wch;
    float *xd, *bgwo;
    int *din, *dout_, *oin, *oout, *cin, *cout_, *bsum, *pos2, *odst;
    cudaGetSymbolAddress(&p, g_xd);          xd    = (float*)p;
    cudaGetSymbolAddress(&p, g_xsh);         xsh   = (__half*)p;
    cudaGetSymbolAddress(&p, g_aggh);        aggh  = (__half*)p;
    cudaGetSymbolAddress(&p, g_hWh);         hWh   = (__half*)p;
    cudaGetSymbolAddress(&p, g_eawh);        eawh  = (__half*)p;
    cudaGetSymbolAddress(&p, g_Weh);         Weh   = (__half*)p;
    cudaGetSymbolAddress(&p, g_Wch);         Wch   = (__half*)p;
    cudaGetSymbolAddress(&p, g_bgwo);        bgwo  = (float*)p;
    cudaGetSymbolAddress(&p, g_deg_in);      din   = (int*)p;
    cudaGetSymbolAddress(&p, g_deg_out);     dout_ = (int*)p;
    cudaGetSymbolAddress(&p, g_off_in);      oin   = (int*)p;
    cudaGetSymbolAddress(&p, g_off_out);     oout  = (int*)p;
    cudaGetSymbolAddress(&p, g_cur_in);      cin   = (int*)p;
    cudaGetSymbolAddress(&p, g_cur_out);     cout_ = (int*)p;
    cudaGetSymbolAddress(&p, g_bsum);        bsum  = (int*)p;
    cudaGetSymbolAddress(&p, g_pos2);        pos2  = (int*)p;
    cudaGetSymbolAddress(&p, g_csr_out_dst); odst  = (int*)p;

    const size_t mm_shmem  = 69632;           // sA + sB
    const size_t eaw_shmem = 70656;           // sA + sB + sSrc + sPos
    cudaFuncSetAttribute(k_mm<true,  false>, cudaFuncAttributeMaxDynamicSharedMemorySize, (int)mm_shmem);
    cudaFuncSetAttribute(k_mm<true,  true >, cudaFuncAttributeMaxDynamicSharedMemorySize, (int)mm_shmem);
    cudaFuncSetAttribute(k_mm<false, true >, cudaFuncAttributeMaxDynamicSharedMemorySize, (int)mm_shmem);
    cudaFuncSetAttribute(k_eaw,              cudaFuncAttributeMaxDynamicSharedMemorySize, (int)eaw_shmem);

    const int gblocks = NPAD / 128;           // 391
    const int eblocks = N_EDGES / 128;        // 6250
    const int nwarp_blocks = (N_NODES * 32 + 255) / 256;   // 6250

    cudaMemsetAsync(din,   0, N_NODES * sizeof(int));
    cudaMemsetAsync(dout_, 0, N_NODES * sizeof(int));

    k_f2h<<<(3 * WSZ + 255) / 256, 256>>>(We, Weh, 3 * WSZ);
    k_hist<<<(N_EDGES + 255) / 256, 256>>>(ei, din, dout_);
    k_mm<true, true ><<<gblocks, 256, mm_shmem>>>(x, Weh + WSZ, nullptr, xsh, N_NODES);

    // hierarchical CSR offset scan (replaces 70us 2-block scan)
    k_blocksum<<<2 * SCAN_BLOCKS, 512>>>(din, dout_, bsum);
    k_bscan<<<2, 128>>>(bsum, oin, oout);
    k_scatteroff<<<2 * SCAN_BLOCKS, 512>>>(din, dout_, bsum, oin, cin, oout, cout_);

    k_scatteridx<<<(N_EDGES + 255) / 256, 256>>>(ei, cin, cout_, pos2, odst);

    // edge GEMM + xs fold, scatter-written into in-CSR order
    k_eaw<<<eblocks, 256, eaw_shmem>>>(ea, ei, xsh, pos2, Weh + 2 * WSZ, eawh);

    k_wc<<<64, 256>>>(Wg, Wo, Wch);
    k_bgwo<<<1, 128>>>(bg, Wo, bgwo);
    k_mm<true, false><<<gblocks, 256, mm_shmem>>>(x, Weh, be, xd, N_NODES);   // be folded

    // fully sequential aggregation
    k_agg<<<nwarp_blocks, 256>>>(oin, xd, eawh, aggh);

    // hW = agg @ (Wg@Wo) + bg@Wo
    k_mm<false, true><<<gblocks, 256, mm_shmem>>>(aggh, Wch, bgwo, hWh, NPAD);

    // out[n] = bo + sum hW[dst] over out-edges
    k_out<<<nwarp_blocks, 256>>>(oout, odst, hWh, bo, out);
}